// round 11
// baseline (speedup 1.0000x reference)
#include <cuda_runtime.h>
#include <cuda_fp16.h>
#include <math.h>
#include <stdint.h>

#define Bb   64
#define Nn   2048
#define Cc   512
#define Ee   32
#define Ac   8
#define INc  512
#define Hc   64
#define Mtot (Bb*Nn)

// -------------------- device scratch (static; allocation-free) -------------
__device__ float  g_sum    [(long long)Mtot*INc];
__device__ float  g_logits [(long long)Mtot*INc];
__device__ float  g_H12    [(long long)Mtot*128];   // [H1 | H2] fp32
__device__ float  g_QK     [(long long)Mtot*64];
__device__ float  g_val    [(long long)Mtot*Ee];
__device__ float  g_Q      [Bb*512];
__device__ float  g_beff   [Bb*64];
__device__ float  g_b12    [128];
__device__ float  g_bsum   [512];
__device__ __half g_WeffH  [Bb*64*512];
__device__ __half g_WsumH  [512*576];
__device__ __half g_WsumL  [512*576];
__device__ __half g_W12H   [128*32];
__device__ __half g_Wa2H   [512*64];

// ========================== helpers ========================================
__device__ __forceinline__ uint32_t smem_u32(const void* p) {
    uint32_t a;
    asm("{ .reg .u64 t; cvta.to.shared.u64 t, %1; cvt.u32.u64 %0, t; }" : "=r"(a) : "l"(p));
    return a;
}
// 8 fp32 -> hi f16x8 (16B at addr), lo f16x8 (16B at addr+lo_off)
__device__ __forceinline__ void split8h(uint32_t addr, uint32_t lo_off, float4 a0, float4 a1) {
    __half2 h0 = __floats2half2_rn(a0.x, a0.y);
    __half2 h1 = __floats2half2_rn(a0.z, a0.w);
    __half2 h2 = __floats2half2_rn(a1.x, a1.y);
    __half2 h3 = __floats2half2_rn(a1.z, a1.w);
    float2 f0 = __half22float2(h0), f1 = __half22float2(h1);
    float2 f2 = __half22float2(h2), f3 = __half22float2(h3);
    __half2 l0 = __floats2half2_rn(a0.x - f0.x, a0.y - f0.y);
    __half2 l1 = __floats2half2_rn(a0.z - f1.x, a0.w - f1.y);
    __half2 l2 = __floats2half2_rn(a1.x - f2.x, a1.y - f2.y);
    __half2 l3 = __floats2half2_rn(a1.z - f3.x, a1.w - f3.y);
    asm volatile("st.shared.v4.b32 [%0], {%1,%2,%3,%4};"
        :: "r"(addr), "r"(*(uint32_t*)&h0), "r"(*(uint32_t*)&h1), "r"(*(uint32_t*)&h2), "r"(*(uint32_t*)&h3));
    asm volatile("st.shared.v4.b32 [%0], {%1,%2,%3,%4};"
        :: "r"(addr + lo_off), "r"(*(uint32_t*)&l0), "r"(*(uint32_t*)&l1), "r"(*(uint32_t*)&l2), "r"(*(uint32_t*)&l3));
}
#define LDSM_X4(r0, r1, r2, r3, addr) \
    asm volatile("ldmatrix.sync.aligned.m8n8.x4.shared.b16 {%0,%1,%2,%3}, [%4];" \
        : "=r"(r0), "=r"(r1), "=r"(r2), "=r"(r3) : "r"(addr))
__device__ __forceinline__ void mma16816h(float d[4], const uint32_t a[4], const uint32_t b[2]) {
    asm volatile("mma.sync.aligned.m16n8k16.row.col.f32.f16.f16.f32 "
        "{%0,%1,%2,%3},{%4,%5,%6,%7},{%8,%9},{%0,%1,%2,%3};"
        : "+f"(d[0]), "+f"(d[1]), "+f"(d[2]), "+f"(d[3])
        : "r"(a[0]), "r"(a[1]), "r"(a[2]), "r"(a[3]), "r"(b[0]), "r"(b[1]));
}
// fp16 accumulator variant (2 regs = 4 halves, same element mapping as fp32 d0..d3)
__device__ __forceinline__ void mma16816hh(uint32_t d[2], const uint32_t a[4], const uint32_t b[2]) {
    asm volatile("mma.sync.aligned.m16n8k16.row.col.f16.f16.f16.f16 "
        "{%0,%1},{%2,%3,%4,%5},{%6,%7},{%0,%1};"
        : "+r"(d[0]), "+r"(d[1])
        : "r"(a[0]), "r"(a[1]), "r"(a[2]), "r"(a[3]), "r"(b[0]), "r"(b[1]));
}
#define STS128(addr, v) \
    asm volatile("st.shared.v4.b32 [%0], {%1,%2,%3,%4};" \
        :: "r"(addr), "r"((v).x), "r"((v).y), "r"((v).z), "r"((v).w))

// ===== mixed-term GEMM, double-buffered, mixed fp32/fp16 accumulators =======
// TERMS==2: MMAs = Ah*Wh (fp32 acc) + Al*Wh (fp16 acc).
// TERMS==3: MMAs = Ah*Wh (fp32 acc) + Al*Wh + Ah*Wl (both fp16 acc).
// C = A(MxK) W(NxK)^T + bias; A = A1 (lda1,K1) concat A2 (lda2,K2), fp32.
// Block tile 128 x NT, NT = 64. 8 warps: 4 over M, 2 over N.
template<int NT, int TERMS, bool GELU>
__global__ __launch_bounds__(256, 2)
void mma_gemm(const float* __restrict__ A1, int lda1, int K1,
              const float* __restrict__ A2, int lda2, int K2,
              const __half* __restrict__ Wh, const __half* __restrict__ Wl,
              const float* __restrict__ bias,
              float* __restrict__ C, int ldc,
              long long az, long long wz, long long bz, long long cz)
{
    constexpr uint32_t BLO = NT * 80;                  // B lo-plane offset
    constexpr int NBPL = (TERMS == 3) ? 2 : 1;
    constexpr uint32_t BUFSZ = 2 * 10240 + NBPL * NT * 80;
    extern __shared__ __align__(128) uint8_t smem_dyn[];
    const uint32_t SA = smem_u32(smem_dyn);            // A hi; lo at +10240
    const uint32_t SB = SA + 20480;
    const int Kt = K1 + K2;
    const int tid = threadIdx.x;
    const int wid = tid >> 5, lid = tid & 31;
    const int warp_m = wid & 3, warp_n = wid >> 2;
    const long long row0 = (long long)blockIdx.y * 128;
    const int col0 = blockIdx.x * NT;
    const int z = blockIdx.z;
    const float*  A1z = A1 + (long long)z * az;
    const __half* Whz = Wh + (long long)z * wz;
    float* Cz = C + (long long)z * cz;

    const int lr = tid >> 1, kh = tid & 1;
    const uint32_t sAst = SA + (uint32_t)lr * 80 + (uint32_t)kh * 32;
    const uint32_t sBst = SB + (uint32_t)lr * 80 + (uint32_t)kh * 32;
    const bool bvalid = lr < NT;
    const long long boffg = (long long)(col0 + lr) * Kt + kh * 16;

    uint32_t aoff[2];
#pragma unroll
    for (int mt = 0; mt < 2; mt++) {
        int rowm = warp_m * 32 + mt * 16 + (lid & 7) + ((lid >> 3) & 1) * 8;
        aoff[mt] = SA + (uint32_t)rowm * 80 + (uint32_t)((lid >> 4) & 1) * 16;
    }
    constexpr int NTP = NT / 32;
    uint32_t boff[NTP];
#pragma unroll
    for (int ntp = 0; ntp < NTP; ntp++) {
        int rown = warp_n * (NT / 2) + ntp * 16 + (lid & 7) + ((lid >> 4) & 1) * 8;
        boff[ntp] = SB + (uint32_t)rown * 80 + (uint32_t)((lid >> 3) & 1) * 16;
    }

    float acc[2][NT / 16][4];           // hi*hi, fp32
    uint32_t acch[2][NT / 16][2];       // lo terms, fp16 accum
#pragma unroll
    for (int i = 0; i < 2; i++)
#pragma unroll
        for (int j = 0; j < NT / 16; j++) {
#pragma unroll
            for (int q = 0; q < 4; q++) acc[i][j][q] = 0.f;
            acch[i][j][0] = 0u; acch[i][j][1] = 0u;
        }

    const int nchunk = Kt >> 5;

    // prefetch chunk 0
    float4 a00, a01, a10, a11;
    uint4 pb0, pb1, pbl0, pbl1;
    {
        const float* Arow = A1z + (row0 + lr) * (long long)lda1 + kh * 16;
        a00 = *(const float4*)(Arow);
        a01 = *(const float4*)(Arow + 4);
        a10 = *(const float4*)(Arow + 8);
        a11 = *(const float4*)(Arow + 12);
        if (bvalid) {
            pb0 = *(const uint4*)(Whz + boffg);
            pb1 = *(const uint4*)(Whz + boffg + 8);
            if (TERMS == 3) {
                pbl0 = *(const uint4*)(Wl + boffg);
                pbl1 = *(const uint4*)(Wl + boffg + 8);
            }
        }
    }

    for (int ch = 0; ch < nchunk; ch++) {
        const uint32_t bo = (uint32_t)(ch & 1) * BUFSZ;
        split8h(sAst + bo,      10240, a00, a01);
        split8h(sAst + bo + 16, 10240, a10, a11);
        if (bvalid) {
            STS128(sBst + bo,      pb0);
            STS128(sBst + bo + 16, pb1);
            if (TERMS == 3) {
                STS128(sBst + bo + BLO,      pbl0);
                STS128(sBst + bo + BLO + 16, pbl1);
            }
        }
        __syncthreads();

        if (ch + 1 < nchunk) {
            const int k0 = (ch + 1) * 32;
            const float* Arow = (k0 < K1)
                ? A1z + (row0 + lr) * (long long)lda1 + k0 + kh * 16
                : A2  + (row0 + lr) * (long long)lda2 + (k0 - K1) + kh * 16;
            a00 = *(const float4*)(Arow);
            a01 = *(const float4*)(Arow + 4);
            a10 = *(const float4*)(Arow + 8);
            a11 = *(const float4*)(Arow + 12);
            if (bvalid) {
                pb0 = *(const uint4*)(Whz + boffg + k0);
                pb1 = *(const uint4*)(Whz + boffg + k0 + 8);
                if (TERMS == 3) {
                    pbl0 = *(const uint4*)(Wl + boffg + k0);
                    pbl1 = *(const uint4*)(Wl + boffg + k0 + 8);
                }
            }
        }

#pragma unroll
        for (int khalf = 0; khalf < 2; khalf++) {
            const uint32_t kb = (uint32_t)khalf * 32 + bo;
            uint32_t Ah[2][4], Al[2][4];
#pragma unroll
            for (int mt = 0; mt < 2; mt++) {
                LDSM_X4(Ah[mt][0], Ah[mt][1], Ah[mt][2], Ah[mt][3], aoff[mt] + kb);
                LDSM_X4(Al[mt][0], Al[mt][1], Al[mt][2], Al[mt][3], aoff[mt] + kb + 10240);
            }
#pragma unroll
            for (int ntp = 0; ntp < NTP; ntp++) {
                uint32_t Bh[4], Bl[4];
                LDSM_X4(Bh[0], Bh[1], Bh[2], Bh[3], boff[ntp] + kb);
                if (TERMS == 3)
                    LDSM_X4(Bl[0], Bl[1], Bl[2], Bl[3], boff[ntp] + kb + BLO);
#pragma unroll
                for (int mt = 0; mt < 2; mt++) {
#pragma unroll
                    for (int nt2 = 0; nt2 < 2; nt2++) {
                        float* d = acc[mt][ntp * 2 + nt2];
                        uint32_t* dh = acch[mt][ntp * 2 + nt2];
                        mma16816h(d, Ah[mt], &Bh[nt2 * 2]);        // hi*Whi (fp32)
                        mma16816hh(dh, Al[mt], &Bh[nt2 * 2]);      // lo*Whi (fp16)
                        if (TERMS == 3)
                            mma16816hh(dh, Ah[mt], &Bl[nt2 * 2]);  // hi*Wlo (fp16)
                    }
                }
            }
        }
    }

    const int g = lid >> 2, t = lid & 3;
    const float* biz = bias ? bias + (long long)z * bz : nullptr;
#pragma unroll
    for (int mt = 0; mt < 2; mt++) {
        long long rA = row0 + warp_m * 32 + mt * 16 + g;
        long long rB = rA + 8;
#pragma unroll
        for (int nt = 0; nt < NT / 16; nt++) {
            int col = col0 + warp_n * (NT / 2) + nt * 8 + 2 * t;
            float b0 = biz ? biz[col] : 0.f;
            float b1 = biz ? biz[col + 1] : 0.f;
            float* d = acc[mt][nt];
            float2 e0 = __half22float2(*(__half2*)&acch[mt][nt][0]);
            float2 e1 = __half22float2(*(__half2*)&acch[mt][nt][1]);
            float o0 = d[0] + e0.x + b0, o1 = d[1] + e0.y + b1;
            float o2 = d[2] + e1.x + b0, o3 = d[3] + e1.y + b1;
            if (GELU) {
                o0 = 0.5f * o0 * (1.f + erff(o0 * 0.70710678118654752f));
                o1 = 0.5f * o1 * (1.f + erff(o1 * 0.70710678118654752f));
                o2 = 0.5f * o2 * (1.f + erff(o2 * 0.70710678118654752f));
                o3 = 0.5f * o3 * (1.f + erff(o3 * 0.70710678118654752f));
            }
            *(float2*)(Cz + rA * ldc + col) = make_float2(o0, o1);
            *(float2*)(Cz + rB * ldc + col) = make_float2(o2, o3);
        }
    }
}

// -------------------- fp32 -> fp16 (round) ---------------------------------
__global__ __launch_bounds__(256)
void tofp16(const float* __restrict__ s, __half* __restrict__ d, int n)
{
    int i = (blockIdx.x * 256 + threadIdx.x) * 8;
    if (i >= n) return;
    float4 a = *(const float4*)(s + i);
    float4 b = *(const float4*)(s + i + 4);
    __half2 h0 = __floats2half2_rn(a.x, a.y), h1 = __floats2half2_rn(a.z, a.w);
    __half2 h2 = __floats2half2_rn(b.x, b.y), h3 = __floats2half2_rn(b.z, b.w);
    *(uint4*)(d + i) = make_uint4(*(uint32_t*)&h0, *(uint32_t*)&h1, *(uint32_t*)&h2, *(uint32_t*)&h3);
}

// ---- Q = node[:, 0, :] @ Wq_w^T + Wq_b; grid (Bb, 8), 4 thr/output --------
__global__ __launch_bounds__(256)
void q_kernel(const float* __restrict__ node, const float* __restrict__ Wq_w,
              const float* __restrict__ Wq_b)
{
    __shared__ __align__(16) float xs[512];
    const int b = blockIdx.x, part = blockIdx.y, tid = threadIdx.x;
    const float* xr = node + (long long)b * Nn * Cc;
    xs[tid]       = xr[tid];
    xs[tid + 256] = xr[tid + 256];
    __syncthreads();
    const int jj = tid >> 2;        // 0..63
    const int t4 = tid & 3;         // k-quarter
    const int j = part * 64 + jj;
    const float4* x4 = (const float4*)xs + t4 * 32;
    const float4* w4 = (const float4*)(Wq_w + (long long)j * 512) + t4 * 32;
    float acc0 = 0.f, acc1 = 0.f;   // 2-way ILP
#pragma unroll 8
    for (int k = 0; k < 32; k += 2) {
        float4 w0 = w4[k], x0 = x4[k];
        float4 w1 = w4[k + 1], x1 = x4[k + 1];
        acc0 += w0.x*x0.x + w0.y*x0.y + w0.z*x0.z + w0.w*x0.w;
        acc1 += w1.x*x1.x + w1.y*x1.y + w1.z*x1.z + w1.w*x1.w;
    }
    float acc = acc0 + acc1;
    acc += __shfl_xor_sync(0xffffffffu, acc, 1);
    acc += __shfl_xor_sync(0xffffffffu, acc, 2);
    if (t4 == 0) g_Q[b * 512 + j] = acc + Wq_b[j];
}

// ------ Weff[b,e2,:] = sum_a Q[b,a,e2] * Wk_w[a*64+e2,:] -> fp16 -----------
__global__ __launch_bounds__(256)
void weff_kernel(const float* __restrict__ Wk_w, const float* __restrict__ Wk_b)
{
    __shared__ float Qs[512];
    const int b = blockIdx.x, part = blockIdx.y, tid = threadIdx.x;
    Qs[tid]       = g_Q[b * 512 + tid];
    Qs[tid + 256] = g_Q[b * 512 + 256 + tid];
    __syncthreads();
    const int i0 = part * 4096;
    for (int idx = i0 + tid; idx < i0 + 4096; idx += 256) {
        int e2 = idx >> 9, c = idx & 511;
        float acc = 0.f;
#pragma unroll
        for (int a = 0; a < 8; a++)
            acc += Qs[a * 64 + e2] * Wk_w[(long long)(a * 64 + e2) * 512 + c];
        g_WeffH[(long long)b * 32768 + idx] = __float2half_rn(acc);
    }
    if (part == 0 && tid < 64) {
        float acc = 0.f;
#pragma unroll
        for (int a = 0; a < 8; a++) acc += Qs[a * 64 + tid] * Wk_b[a * 64 + tid];
        g_beff[b * 64 + tid] = acc;
    }
}

// -------------------- weight prep ------------------------------------------
__global__ void prep12(const float* __restrict__ Wa_w1, const float* __restrict__ et_w1,
                       const float* __restrict__ et_b1)
{
    int i = blockIdx.x * 256 + threadIdx.x;
    if (i < 4096) {
        int h = i >> 5, k = i & 31;
        float v = (h < 64) ? Wa_w1[h * 32 + k] : et_w1[(h - 64) * 32 + k];
        g_W12H[i] = __float2half_rn(v);
    }
    if (i < 128) g_b12[i] = (i < 64) ? 0.f : et_b1[i - 64];
}
__global__ void prepsum(const float* __restrict__ nt_w, const float* __restrict__ nt_b,
                        const float* __restrict__ et_w2, const float* __restrict__ et_b2)
{
    int n = blockIdx.x, t = threadIdx.x;
    for (int k = t; k < 576; k += 256) {
        float v = (k < 512) ? nt_w[n * 512 + k] : et_w2[n * 64 + (k - 512)];
        __half hh = __float2half_rn(v);
        g_WsumH[n * 576 + k] = hh;
        g_WsumL[n * 576 + k] = __float2half_rn(v - __half2float(hh));
    }
    if (t == 0) g_bsum[n] = nt_b[n] + et_b2[n];
}

// -------------------- val = selu(rho(QKlo*ew) + QKhi*emb1 + emb2) ----------
__global__ __launch_bounds__(256)
void val_kernel(const float* __restrict__ edge, const float* __restrict__ emb1,
                const float* __restrict__ emb2, const float* __restrict__ Wew)
{
    __shared__ float WewT[32 * 32];   // [j][e]
    __shared__ float er[8][32];
    const int tid = threadIdx.x;
    const long long row0 = (long long)blockIdx.x * 8;
    for (int i = tid; i < 1024; i += 256) WewT[(i & 31) * 32 + (i >> 5)] = Wew[i];
    er[tid >> 5][tid & 31] = edge[row0 * 32 + tid];
    __syncthreads();

    const int r = tid >> 5, e = tid & 31;
    const long long row = row0 + r;
    float ew = 0.f;
#pragma unroll
    for (int j = 0; j < 32; j++) ew += er[r][j] * WewT[j * 32 + e];
    float qk  = g_QK[row * 64 + e];
    float qkh = g_QK[row * 64 + 32 + e];
    float x = qk * ew;
    float rr = (x > 0.f) ? sqrtf(x) : -sqrtf(-x);
    float v = rr + qkh * emb1[row * 32 + e] + emb2[row * 32 + e];
    const float sc = 1.0507009873554805f, al = 1.6732632423543772f;
    float s = (v > 0.f) ? sc * v : sc * al * (expf(v) - 1.f);
    g_val[row * 32 + e] = s;
}

// ---- fused tail: 2 passes, __expf, single tmp write ------------------------
__global__ __launch_bounds__(512)
void tail_kernel(float* __restrict__ d_tmp, float* __restrict__ outp)
{
    __shared__ float4 redm[16][32];
    __shared__ float4 reds[16][32];
    __shared__ float4 redu[16][32];
    const int b = blockIdx.y, cb = blockIdx.x;
    const int slice = threadIdx.x >> 5, lane = threadIdx.x & 31;
    const long long lgbase  = (long long)b * 2048 * 128 + cb * 32 + lane;
    const long long tmpbase = (long long)b * 2047 * 128 + cb * 32 + lane;
    const float4* LG = (const float4*)g_logits;
    const float4* SM = (const float4*)g_sum;
    float4* TMP = (float4*)d_tmp;
    const int n0 = 1 + slice * 128;
    const int n1 = min(2048, n0 + 128);

    float mx=-1e30f, my=-1e30f, mz=-1e30f, mw=-1e30f;
    float sx=0.f, sy=0.f, sz=0.f, sw=0.f;
    float ux=0.f, uy=0.f, uz=0.f, uw=0.f;
#pragma unroll 4
    for (int n = n0; n < n1; n++) {
        float4 x  = LG[lgbase + (long long)n * 128];
        float4 sm = SM[lgbase + (long long)n * 128];
        if (x.x > mx) { float f = __expf(mx - x.x); sx = sx * f + 1.f; ux = fmaxf(ux * f, fabsf(sm.x)); mx = x.x; }
        else          { float e = __expf(x.x - mx); sx += e; ux = fmaxf(ux, fabsf(sm.x) * e); }
        if (x.y > my) { float f = __expf(my - x.y); sy = sy * f + 1.f; uy = fmaxf(uy * f, fabsf(sm.y)); my = x.y; }
        else          { float e = __expf(x.y - my); sy += e; uy = fmaxf(uy, fabsf(sm.y) * e); }
        if (x.z > mz) { float f = __expf(mz - x.z); sz = sz * f + 1.f; uz = fmaxf(uz * f, fabsf(sm.z)); mz = x.z; }
        else          { float e = __expf(x.z - mz); sz += e; uz = fmaxf(uz, fabsf(sm.z) * e); }
        if (x.w > mw) { float f = __expf(mw - x.w); sw = sw * f + 1.f; uw = fmaxf(uw * f, fabsf(sm.w)); mw = x.w; }
        else          { float e = __expf(x.w - mw); sw += e; uw = fmaxf(uw, fabsf(sm.w) * e); }
    }
    redm[slice][lane] = make_float4(mx, my, mz, mw);
    reds[slice][lane] = make_float4(sx, sy, sz, sw);
    redu[slice][lane] = make_float4(ux, uy, uz, uw);
    __syncthreads();
    float Mx=-1e30f, My=-1e30f, Mz=-1e30f, Mw=-1e30f;
#pragma unroll
    for (int k = 0; k < 16; k++) {
        float4 fm = redm[k][lane];
        Mx = fmaxf(Mx, fm.x); My = fmaxf(My, fm.y);
        Mz = fmaxf(Mz, fm.z); Mw = fmaxf(Mw, fm.w);
    }
    float Sx=0.f, Sy=0.f, Sz=0.f, Sw=0.f;
    float Ux=0.f, Uy=0.f, Uz=0.f, Uw=0.f;
#pragma unroll
    for (int k = 0; k < 16; k++) {
        float4 fm = redm[k][lane];
        float4 fs = reds[k][lane];
        float4 fu = redu[k][lane];
        float ex = __expf(fm.x - Mx), ey = __expf(fm.y - My);
        float ez = __expf(fm.z - Mz), ew = __expf(fm.w - Mw);
        Sx += fs.x * ex; Sy += fs.y * ey; Sz += fs.z * ez; Sw += fs.w * ew;
        Ux = fmaxf(Ux, fu.x * ex); Uy = fmaxf(Uy, fu.y * ey);
        Uz = fmaxf(Uz, fu.z * ez); Uw = fmaxf(Uw, fu.w * ew);
    }
    const float ivx = 1.f / Sx, ivy = 1.f / Sy, ivz = 1.f / Sz, ivw = 1.f / Sw;
    const float tux = Ux * 0.1f, tuy = Uy * 0.1f, tuz = Uz * 0.1f, tuw = Uw * 0.1f;

    float cx=0.f, cy=0.f, cz2=0.f, cw=0.f;
#pragma unroll 4
    for (int n = n0; n < n1; n++) {
        float4 x  = LG[lgbase + (long long)n * 128];
        float4 sm = SM[lgbase + (long long)n * 128];
        float ex = __expf(x.x - Mx), ey = __expf(x.y - My);
        float ez = __expf(x.z - Mz), ew = __expf(x.w - Mw);
        float uxx = sm.x * ex, uyy = sm.y * ey, uzz = sm.z * ez, uww = sm.w * ew;
        float tx = (fabsf(uxx) >= tux) ? uxx * ivx : 0.f;
        float ty = (fabsf(uyy) >= tuy) ? uyy * ivy : 0.f;
        float tz = (fabsf(uzz) >= tuz) ? uzz * ivz : 0.f;
        float tw = (fabsf(uww) >= tuw) ? uww * ivw : 0.f;
        TMP[tmpbase + (long long)(n - 1) * 128] = make_float4(tx, ty, tz, tw);
        cx += tx; cy += ty; cz2 += tz; cw += tw;
    }
    redm[slice][lane] = make_float4(cx, cy, cz2, cw);
    __syncthreads();
    if (slice == 0) {
        float4 tot = make_float4(0.f, 0.f, 0.f, 0.f);
#pragma unroll
        for (int k = 0; k < 16; k++) {
            float4 f = redm[k][lane];
            tot.x += f.x; tot.y += f.y; tot.z += f.z; tot.w += f.w;
        }
        ((float4*)outp)[(long long)b * 128 + cb * 32 + lane] = tot;
    }
}

// ---------------------------------------------------------------------------
extern "C" void kernel_launch(void* const* d_in, const int* in_sizes, int n_in,
                              void* d_out, int out_size)
{
    const float* node  = (const float*)d_in[0];
    const float* edge  = (const float*)d_in[1];
    const float* emb1  = (const float*)d_in[2];
    const float* emb2  = (const float*)d_in[3];
    const float* Wq_w  = (const float*)d_in[4];
    const float* Wq_b  = (const float*)d_in[5];
    const float* Wk_w  = (const float*)d_in[6];
    const float* Wk_b  = (const float*)d_in[7];
    const float* Wew_w = (const float*)d_in[8];
    const float* Wa_w1 = (const float*)d_in[9];
    const float* Wa_w2 = (const float*)d_in[10];
    const float* nt_w  = (const float*)d_in[11];
    const float* nt_b  = (const float*)d_in[12];
    const float* et_w1 = (const float*)d_in[13];
    const float* et_b1 = (const float*)d_in[14];
    const float* et_w2 = (const float*)d_in[15];
    const float* et_b2 = (const float*)d_in[16];

    float* outp  = (float*)d_out;            // (B, IN) first
    float* d_tmp = outp + Bb * INc;          // then (B, N-1, IN)

    void *pSum, *pLG, *pH12, *pQK, *pVal, *pBeff, *pB12, *pBsum;
    void *pWeH, *pWsH, *pWsL, *pW12H, *pWa2H;
    cudaGetSymbolAddress(&pSum,  g_sum);
    cudaGetSymbolAddress(&pLG,   g_logits);
    cudaGetSymbolAddress(&pH12,  g_H12);
    cudaGetSymbolAddress(&pQK,   g_QK);
    cudaGetSymbolAddress(&pVal,  g_val);
    cudaGetSymbolAddress(&pBeff, g_beff);
    cudaGetSymbolAddress(&pB12,  g_b12);
    cudaGetSymbolAddress(&pBsum, g_bsum);
    cudaGetSymbolAddress(&pWeH,  g_WeffH);
    cudaGetSymbolAddress(&pWsH,  g_WsumH);
    cudaGetSymbolAddress(&pWsL,  g_WsumL);
    cudaGetSymbolAddress(&pW12H, g_W12H);
    cudaGetSymbolAddress(&pWa2H, g_Wa2H);

    // dynamic smem limits (idempotent host calls; no allocation)
    // NT=64: TERMS=2 stage = 25600B (x2 = 51200); TERMS=3 stage = 30720B (x2 = 61440)
    cudaFuncSetAttribute(mma_gemm<64, 2, false>, cudaFuncAttributeMaxDynamicSharedMemorySize, 51200);
    cudaFuncSetAttribute(mma_gemm<64, 2, true>,  cudaFuncAttributeMaxDynamicSharedMemorySize, 51200);
    cudaFuncSetAttribute(mma_gemm<64, 3, false>, cudaFuncAttributeMaxDynamicSharedMemorySize, 61440);

    // weight prep (tiny, one-time per launch)
    tofp16<<<16, 256>>>(Wa_w2, (__half*)pWa2H, 512 * 64);
    prep12<<<16, 256>>>(Wa_w1, et_w1, et_b1);
    prepsum<<<512, 256>>>(nt_w, nt_b, et_w2, et_b2);

    // Q -> Weff/beff -> QK (batched N=64 GEMM, K=512, 2-term)
    q_kernel<<<dim3(Bb, 8), 256>>>(node, Wq_w, Wq_b);
    weff_kernel<<<dim3(Bb, 8), 256>>>(Wk_w, Wk_b);
    mma_gemm<64, 2, false><<<dim3(1, Nn / 128, Bb), 256, 51200>>>(
        node, Cc, Cc, nullptr, 0, 0,
        (const __half*)pWeH, nullptr, (const float*)pBeff, (float*)pQK, 64,
        (long long)Nn * Cc, 64LL * 512, 64LL, (long long)Nn * 64);

    // val
    val_kernel<<<Mtot / 8, 256>>>(edge, emb1, emb2, Wew_w);

    // H12 = gelu(val @ W12^T + b12)   (M x 128, K=32, 2-term)
    mma_gemm<64, 2, true><<<dim3(2, Mtot / 128, 1), 256, 51200>>>(
        (const float*)pVal, 32, 32, nullptr, 0, 0,
        (const __half*)pW12H, nullptr, (const float*)pB12, (float*)pH12, 128, 0, 0, 0, 0);

    // logits = H1 @ Wa_w2^T           (M x 512, K=64, 2-term)
    mma_gemm<64, 2, false><<<dim3(8, Mtot / 128, 1), 256, 51200>>>(
        (const float*)pH12, 128, 64, nullptr, 0, 0,
        (const __half*)pWa2H, nullptr, nullptr, (float*)pLG, INc, 0, 0, 0, 0);

    // sum = node @ nt_w^T + H2 @ et_w2^T + (nt_b + et_b2)  (K=576, 3-term)
    mma_gemm<64, 3, false><<<dim3(8, Mtot / 128, 1), 256, 61440>>>(
        node, Cc, Cc, (const float*)pH12 + 64, 128, 64,
        (const __half*)pWsH, (const __half*)pWsL, (const float*)pBsum,
        (float*)pSum, INc, 0, 0, 0, 0);

    // fused softmax + combine + threshold + mask + colsum
    tail_kernel<<<dim3(4, Bb), 512>>>(d_tmp, outp);
}

// round 12
// speedup vs baseline: 1.1232x; 1.1232x over previous
#include <cuda_runtime.h>
#include <cuda_fp16.h>
#include <math.h>
#include <stdint.h>

#define Bb   64
#define Nn   2048
#define Cc   512
#define Ee   32
#define Ac   8
#define INc  512
#define Hc   64
#define Mtot (Bb*Nn)

// -------------------- device scratch (static; allocation-free) -------------
__device__ float  g_sum    [(long long)Mtot*INc];
__device__ float  g_logits [(long long)Mtot*INc];
__device__ float  g_H12    [(long long)Mtot*128];   // [H1 | H2] fp32
__device__ float  g_QK     [(long long)Mtot*64];
__device__ float  g_Q      [Bb*512];
__device__ float  g_beff   [Bb*64];
__device__ float  g_bsum   [512];
__device__ __half g_WeffH  [Bb*64*512];
__device__ __half g_WsumH  [512*576];
__device__ __half g_WsumL  [512*576];
__device__ __half g_Wa2H   [512*64];

// ========================== helpers ========================================
__device__ __forceinline__ uint32_t smem_u32(const void* p) {
    uint32_t a;
    asm("{ .reg .u64 t; cvta.to.shared.u64 t, %1; cvt.u32.u64 %0, t; }" : "=r"(a) : "l"(p));
    return a;
}
// 8 fp32 -> hi f16x8 (16B at addr), lo f16x8 (16B at addr+lo_off)
__device__ __forceinline__ void split8h(uint32_t addr, uint32_t lo_off, float4 a0, float4 a1) {
    __half2 h0 = __floats2half2_rn(a0.x, a0.y);
    __half2 h1 = __floats2half2_rn(a0.z, a0.w);
    __half2 h2 = __floats2half2_rn(a1.x, a1.y);
    __half2 h3 = __floats2half2_rn(a1.z, a1.w);
    float2 f0 = __half22float2(h0), f1 = __half22float2(h1);
    float2 f2 = __half22float2(h2), f3 = __half22float2(h3);
    __half2 l0 = __floats2half2_rn(a0.x - f0.x, a0.y - f0.y);
    __half2 l1 = __floats2half2_rn(a0.z - f1.x, a0.w - f1.y);
    __half2 l2 = __floats2half2_rn(a1.x - f2.x, a1.y - f2.y);
    __half2 l3 = __floats2half2_rn(a1.z - f3.x, a1.w - f3.y);
    asm volatile("st.shared.v4.b32 [%0], {%1,%2,%3,%4};"
        :: "r"(addr), "r"(*(uint32_t*)&h0), "r"(*(uint32_t*)&h1), "r"(*(uint32_t*)&h2), "r"(*(uint32_t*)&h3));
    asm volatile("st.shared.v4.b32 [%0], {%1,%2,%3,%4};"
        :: "r"(addr + lo_off), "r"(*(uint32_t*)&l0), "r"(*(uint32_t*)&l1), "r"(*(uint32_t*)&l2), "r"(*(uint32_t*)&l3));
}
#define LDSM_X4(r0, r1, r2, r3, addr) \
    asm volatile("ldmatrix.sync.aligned.m8n8.x4.shared.b16 {%0,%1,%2,%3}, [%4];" \
        : "=r"(r0), "=r"(r1), "=r"(r2), "=r"(r3) : "r"(addr))
__device__ __forceinline__ void mma16816h(float d[4], const uint32_t a[4], const uint32_t b[2]) {
    asm volatile("mma.sync.aligned.m16n8k16.row.col.f32.f16.f16.f32 "
        "{%0,%1,%2,%3},{%4,%5,%6,%7},{%8,%9},{%0,%1,%2,%3};"
        : "+f"(d[0]), "+f"(d[1]), "+f"(d[2]), "+f"(d[3])
        : "r"(a[0]), "r"(a[1]), "r"(a[2]), "r"(a[3]), "r"(b[0]), "r"(b[1]));
}
#define STS128(addr, v) \
    asm volatile("st.shared.v4.b32 [%0], {%1,%2,%3,%4};" \
        :: "r"(addr), "r"((v).x), "r"((v).y), "r"((v).z), "r"((v).w))

// ===== mixed-term GEMM, double-buffered smem (1 sync per chunk) =============
// TERMS==2: W single fp16 plane; MMAs = Ah*Wh + Al*Wh.
// TERMS==3: W fp16 hi/lo planes;  MMAs = Ah*Wh + Al*Wh + Ah*Wl.
// C = A(MxK) W(NxK)^T + bias; A = A1 (lda1,K1) concat A2 (lda2,K2), fp32.
template<int NT, int TERMS, bool GELU>
__global__ __launch_bounds__(256, 2)
void mma_gemm(const float* __restrict__ A1, int lda1, int K1,
              const float* __restrict__ A2, int lda2, int K2,
              const __half* __restrict__ Wh, const __half* __restrict__ Wl,
              const float* __restrict__ bias,
              float* __restrict__ C, int ldc,
              long long az, long long wz, long long bz, long long cz)
{
    constexpr uint32_t BLO = NT * 80;                  // B lo-plane offset
    constexpr int NBPL = (TERMS == 3) ? 2 : 1;
    constexpr uint32_t BUFSZ = 2 * 10240 + NBPL * NT * 80;
    extern __shared__ __align__(128) uint8_t smem_dyn[];
    const uint32_t SA = smem_u32(smem_dyn);            // A hi; lo at +10240
    const uint32_t SB = SA + 20480;
    const int Kt = K1 + K2;
    const int tid = threadIdx.x;
    const int wid = tid >> 5, lid = tid & 31;
    const int warp_m = wid & 3, warp_n = wid >> 2;
    const long long row0 = (long long)blockIdx.y * 128;
    const int col0 = blockIdx.x * NT;
    const int z = blockIdx.z;
    const float*  A1z = A1 + (long long)z * az;
    const __half* Whz = Wh + (long long)z * wz;
    float* Cz = C + (long long)z * cz;

    const int lr = tid >> 1, kh = tid & 1;
    const uint32_t sAst = SA + (uint32_t)lr * 80 + (uint32_t)kh * 32;
    const uint32_t sBst = SB + (uint32_t)lr * 80 + (uint32_t)kh * 32;
    const bool bvalid = lr < NT;
    const long long boffg = (long long)(col0 + lr) * Kt + kh * 16;

    uint32_t aoff[2];
#pragma unroll
    for (int mt = 0; mt < 2; mt++) {
        int rowm = warp_m * 32 + mt * 16 + (lid & 7) + ((lid >> 3) & 1) * 8;
        aoff[mt] = SA + (uint32_t)rowm * 80 + (uint32_t)((lid >> 4) & 1) * 16;
    }
    constexpr int NTP = NT / 32;
    uint32_t boff[NTP];
#pragma unroll
    for (int ntp = 0; ntp < NTP; ntp++) {
        int rown = warp_n * (NT / 2) + ntp * 16 + (lid & 7) + ((lid >> 4) & 1) * 8;
        boff[ntp] = SB + (uint32_t)rown * 80 + (uint32_t)((lid >> 3) & 1) * 16;
    }

    float acc[2][NT / 16][4];
#pragma unroll
    for (int i = 0; i < 2; i++)
#pragma unroll
        for (int j = 0; j < NT / 16; j++)
#pragma unroll
            for (int q = 0; q < 4; q++) acc[i][j][q] = 0.f;

    const int nchunk = Kt >> 5;

    // prefetch chunk 0
    float4 a00, a01, a10, a11;
    uint4 pb0, pb1, pbl0, pbl1;
    {
        const float* Arow = A1z + (row0 + lr) * (long long)lda1 + kh * 16;
        a00 = *(const float4*)(Arow);
        a01 = *(const float4*)(Arow + 4);
        a10 = *(const float4*)(Arow + 8);
        a11 = *(const float4*)(Arow + 12);
        if (bvalid) {
            pb0 = *(const uint4*)(Whz + boffg);
            pb1 = *(const uint4*)(Whz + boffg + 8);
            if (TERMS == 3) {
                pbl0 = *(const uint4*)(Wl + boffg);
                pbl1 = *(const uint4*)(Wl + boffg + 8);
            }
        }
    }

    for (int ch = 0; ch < nchunk; ch++) {
        const uint32_t bo = (uint32_t)(ch & 1) * BUFSZ;
        split8h(sAst + bo,      10240, a00, a01);
        split8h(sAst + bo + 16, 10240, a10, a11);
        if (bvalid) {
            STS128(sBst + bo,      pb0);
            STS128(sBst + bo + 16, pb1);
            if (TERMS == 3) {
                STS128(sBst + bo + BLO,      pbl0);
                STS128(sBst + bo + BLO + 16, pbl1);
            }
        }
        __syncthreads();

        if (ch + 1 < nchunk) {
            const int k0 = (ch + 1) * 32;
            const float* Arow = (k0 < K1)
                ? A1z + (row0 + lr) * (long long)lda1 + k0 + kh * 16
                : A2  + (row0 + lr) * (long long)lda2 + (k0 - K1) + kh * 16;
            a00 = *(const float4*)(Arow);
            a01 = *(const float4*)(Arow + 4);
            a10 = *(const float4*)(Arow + 8);
            a11 = *(const float4*)(Arow + 12);
            if (bvalid) {
                pb0 = *(const uint4*)(Whz + boffg + k0);
                pb1 = *(const uint4*)(Whz + boffg + k0 + 8);
                if (TERMS == 3) {
                    pbl0 = *(const uint4*)(Wl + boffg + k0);
                    pbl1 = *(const uint4*)(Wl + boffg + k0 + 8);
                }
            }
        }

#pragma unroll
        for (int khalf = 0; khalf < 2; khalf++) {
            const uint32_t kb = (uint32_t)khalf * 32 + bo;
            uint32_t Ah[2][4], Al[2][4];
#pragma unroll
            for (int mt = 0; mt < 2; mt++) {
                LDSM_X4(Ah[mt][0], Ah[mt][1], Ah[mt][2], Ah[mt][3], aoff[mt] + kb);
                LDSM_X4(Al[mt][0], Al[mt][1], Al[mt][2], Al[mt][3], aoff[mt] + kb + 10240);
            }
#pragma unroll
            for (int ntp = 0; ntp < NTP; ntp++) {
                uint32_t Bh[4], Bl[4];
                LDSM_X4(Bh[0], Bh[1], Bh[2], Bh[3], boff[ntp] + kb);
                if (TERMS == 3)
                    LDSM_X4(Bl[0], Bl[1], Bl[2], Bl[3], boff[ntp] + kb + BLO);
#pragma unroll
                for (int mt = 0; mt < 2; mt++) {
#pragma unroll
                    for (int nt2 = 0; nt2 < 2; nt2++) {
                        float* d = acc[mt][ntp * 2 + nt2];
                        mma16816h(d, Ah[mt], &Bh[nt2 * 2]);       // hi*Whi
                        mma16816h(d, Al[mt], &Bh[nt2 * 2]);       // lo*Whi
                        if (TERMS == 3)
                            mma16816h(d, Ah[mt], &Bl[nt2 * 2]);   // hi*Wlo
                    }
                }
            }
        }
    }

    const int g = lid >> 2, t = lid & 3;
    const float* biz = bias ? bias + (long long)z * bz : nullptr;
#pragma unroll
    for (int mt = 0; mt < 2; mt++) {
        long long rA = row0 + warp_m * 32 + mt * 16 + g;
        long long rB = rA + 8;
#pragma unroll
        for (int nt = 0; nt < NT / 16; nt++) {
            int col = col0 + warp_n * (NT / 2) + nt * 8 + 2 * t;
            float b0 = biz ? biz[col] : 0.f;
            float b1 = biz ? biz[col + 1] : 0.f;
            float* d = acc[mt][nt];
            float o0 = d[0] + b0, o1 = d[1] + b1, o2 = d[2] + b0, o3 = d[3] + b1;
            if (GELU) {
                o0 = 0.5f * o0 * (1.f + erff(o0 * 0.70710678118654752f));
                o1 = 0.5f * o1 * (1.f + erff(o1 * 0.70710678118654752f));
                o2 = 0.5f * o2 * (1.f + erff(o2 * 0.70710678118654752f));
                o3 = 0.5f * o3 * (1.f + erff(o3 * 0.70710678118654752f));
            }
            *(float2*)(Cz + rA * ldc + col) = make_float2(o0, o1);
            *(float2*)(Cz + rB * ldc + col) = make_float2(o2, o3);
        }
    }
}

// -------------------- fp32 -> fp16 (round) ---------------------------------
__global__ __launch_bounds__(256)
void tofp16(const float* __restrict__ s, __half* __restrict__ d, int n)
{
    int i = (blockIdx.x * 256 + threadIdx.x) * 8;
    if (i >= n) return;
    float4 a = *(const float4*)(s + i);
    float4 b = *(const float4*)(s + i + 4);
    __half2 h0 = __floats2half2_rn(a.x, a.y), h1 = __floats2half2_rn(a.z, a.w);
    __half2 h2 = __floats2half2_rn(b.x, b.y), h3 = __floats2half2_rn(b.z, b.w);
    *(uint4*)(d + i) = make_uint4(*(uint32_t*)&h0, *(uint32_t*)&h1, *(uint32_t*)&h2, *(uint32_t*)&h3);
}

// ---- Q = node[:, 0, :] @ Wq_w^T + Wq_b; grid (Bb, 8), 4 thr/output --------
__global__ __launch_bounds__(256)
void q_kernel(const float* __restrict__ node, const float* __restrict__ Wq_w,
              const float* __restrict__ Wq_b)
{
    __shared__ __align__(16) float xs[512];
    const int b = blockIdx.x, part = blockIdx.y, tid = threadIdx.x;
    const float* xr = node + (long long)b * Nn * Cc;
    xs[tid]       = xr[tid];
    xs[tid + 256] = xr[tid + 256];
    __syncthreads();
    const int jj = tid >> 2;        // 0..63
    const int t4 = tid & 3;         // k-quarter
    const int j = part * 64 + jj;
    const float4* x4 = (const float4*)xs + t4 * 32;
    const float4* w4 = (const float4*)(Wq_w + (long long)j * 512) + t4 * 32;
    float acc0 = 0.f, acc1 = 0.f;
#pragma unroll 8
    for (int k = 0; k < 32; k += 2) {
        float4 w0 = w4[k], x0 = x4[k];
        float4 w1 = w4[k + 1], x1 = x4[k + 1];
        acc0 += w0.x*x0.x + w0.y*x0.y + w0.z*x0.z + w0.w*x0.w;
        acc1 += w1.x*x1.x + w1.y*x1.y + w1.z*x1.z + w1.w*x1.w;
    }
    float acc = acc0 + acc1;
    acc += __shfl_xor_sync(0xffffffffu, acc, 1);
    acc += __shfl_xor_sync(0xffffffffu, acc, 2);
    if (t4 == 0) g_Q[b * 512 + j] = acc + Wq_b[j];
}

// ------ Weff[b,e2,:] = sum_a Q[b,a,e2] * Wk_w[a*64+e2,:] -> fp16 -----------
__global__ __launch_bounds__(256)
void weff_kernel(const float* __restrict__ Wk_w, const float* __restrict__ Wk_b)
{
    __shared__ float Qs[512];
    const int b = blockIdx.x, part = blockIdx.y, tid = threadIdx.x;
    Qs[tid]       = g_Q[b * 512 + tid];
    Qs[tid + 256] = g_Q[b * 512 + 256 + tid];
    __syncthreads();
    const int i0 = part * 4096;
    for (int idx = i0 + tid; idx < i0 + 4096; idx += 256) {
        int e2 = idx >> 9, c = idx & 511;
        float acc = 0.f;
#pragma unroll
        for (int a = 0; a < 8; a++)
            acc += Qs[a * 64 + e2] * Wk_w[(long long)(a * 64 + e2) * 512 + c];
        g_WeffH[(long long)b * 32768 + idx] = __float2half_rn(acc);
    }
    if (part == 0 && tid < 64) {
        float acc = 0.f;
#pragma unroll
        for (int a = 0; a < 8; a++) acc += Qs[a * 64 + tid] * Wk_b[a * 64 + tid];
        g_beff[b * 64 + tid] = acc;
    }
}

// -------------------- weight prep ------------------------------------------
__global__ void prepsum(const float* __restrict__ nt_w, const float* __restrict__ nt_b,
                        const float* __restrict__ et_w2, const float* __restrict__ et_b2)
{
    int n = blockIdx.x, t = threadIdx.x;
    for (int k = t; k < 576; k += 256) {
        float v = (k < 512) ? nt_w[n * 512 + k] : et_w2[n * 64 + (k - 512)];
        __half hh = __float2half_rn(v);
        g_WsumH[n * 576 + k] = hh;
        g_WsumL[n * 576 + k] = __float2half_rn(v - __half2float(hh));
    }
    if (t == 0) g_bsum[n] = nt_b[n] + et_b2[n];
}

// ---- fused val + H12: val = selu(...); H12 = gelu(val @ W12^T + b12) ------
// 256 threads, 8 rows per block. val kept in smem (fp32), H12 written fp32.
__global__ __launch_bounds__(256)
void val_h12_kernel(const float* __restrict__ edge, const float* __restrict__ emb1,
                    const float* __restrict__ emb2, const float* __restrict__ Wew,
                    const float* __restrict__ Wa_w1, const float* __restrict__ et_w1,
                    const float* __restrict__ et_b1)
{
    __shared__ float WewT[32 * 32];      // [j][e]
    __shared__ float er[8][32];
    __shared__ float vs[8][32];
    __shared__ float W12T[32][132];      // [e][h], padded
    __shared__ float b12s[128];
    const int tid = threadIdx.x;
    const long long row0 = (long long)blockIdx.x * 8;
    for (int i = tid; i < 1024; i += 256) WewT[(i & 31) * 32 + (i >> 5)] = Wew[i];
    er[tid >> 5][tid & 31] = edge[row0 * 32 + tid];
    for (int i = tid; i < 4096; i += 256) {
        int h = i >> 5, e = i & 31;
        W12T[e][h] = (h < 64) ? Wa_w1[h * 32 + e] : et_w1[(h - 64) * 32 + e];
    }
    if (tid < 128) b12s[tid] = (tid < 64) ? 0.f : et_b1[tid - 64];
    __syncthreads();

    {
        const int r = tid >> 5, e = tid & 31;
        const long long row = row0 + r;
        float ew = 0.f;
#pragma unroll
        for (int j = 0; j < 32; j++) ew += er[r][j] * WewT[j * 32 + e];
        float qk  = g_QK[row * 64 + e];
        float qkh = g_QK[row * 64 + 32 + e];
        float x = qk * ew;
        float rr = (x > 0.f) ? sqrtf(x) : -sqrtf(-x);
        float v = rr + qkh * emb1[row * 32 + e] + emb2[row * 32 + e];
        const float sc = 1.0507009873554805f, al = 1.6732632423543772f;
        vs[r][e] = (v > 0.f) ? sc * v : sc * al * (expf(v) - 1.f);
    }
    __syncthreads();

    const int h = tid & 127, half = tid >> 7;
    float w[32];
#pragma unroll
    for (int e = 0; e < 32; e++) w[e] = W12T[e][h];
    const float bb = b12s[h];
#pragma unroll
    for (int rr2 = 0; rr2 < 4; rr2++) {
        const int r = half * 4 + rr2;
        float acc = bb;
#pragma unroll
        for (int e = 0; e < 32; e++) acc = fmaf(vs[r][e], w[e], acc);
        float g = 0.5f * acc * (1.f + erff(acc * 0.70710678118654752f));
        g_H12[(row0 + r) * 128 + h] = g;
    }
}

// ---- fused tail: 2 passes, __expf, single tmp write ------------------------
__global__ __launch_bounds__(512)
void tail_kernel(float* __restrict__ d_tmp, float* __restrict__ outp)
{
    __shared__ float4 redm[16][32];
    __shared__ float4 reds[16][32];
    __shared__ float4 redu[16][32];
    const int b = blockIdx.y, cb = blockIdx.x;
    const int slice = threadIdx.x >> 5, lane = threadIdx.x & 31;
    const long long lgbase  = (long long)b * 2048 * 128 + cb * 32 + lane;
    const long long tmpbase = (long long)b * 2047 * 128 + cb * 32 + lane;
    const float4* LG = (const float4*)g_logits;
    const float4* SM = (const float4*)g_sum;
    float4* TMP = (float4*)d_tmp;
    const int n0 = 1 + slice * 128;
    const int n1 = min(2048, n0 + 128);

    float mx=-1e30f, my=-1e30f, mz=-1e30f, mw=-1e30f;
    float sx=0.f, sy=0.f, sz=0.f, sw=0.f;
    float ux=0.f, uy=0.f, uz=0.f, uw=0.f;
#pragma unroll 4
    for (int n = n0; n < n1; n++) {
        float4 x  = LG[lgbase + (long long)n * 128];
        float4 sm = SM[lgbase + (long long)n * 128];
        if (x.x > mx) { float f = __expf(mx - x.x); sx = sx * f + 1.f; ux = fmaxf(ux * f, fabsf(sm.x)); mx = x.x; }
        else          { float e = __expf(x.x - mx); sx += e; ux = fmaxf(ux, fabsf(sm.x) * e); }
        if (x.y > my) { float f = __expf(my - x.y); sy = sy * f + 1.f; uy = fmaxf(uy * f, fabsf(sm.y)); my = x.y; }
        else          { float e = __expf(x.y - my); sy += e; uy = fmaxf(uy, fabsf(sm.y) * e); }
        if (x.z > mz) { float f = __expf(mz - x.z); sz = sz * f + 1.f; uz = fmaxf(uz * f, fabsf(sm.z)); mz = x.z; }
        else          { float e = __expf(x.z - mz); sz += e; uz = fmaxf(uz, fabsf(sm.z) * e); }
        if (x.w > mw) { float f = __expf(mw - x.w); sw = sw * f + 1.f; uw = fmaxf(uw * f, fabsf(sm.w)); mw = x.w; }
        else          { float e = __expf(x.w - mw); sw += e; uw = fmaxf(uw, fabsf(sm.w) * e); }
    }
    redm[slice][lane] = make_float4(mx, my, mz, mw);
    reds[slice][lane] = make_float4(sx, sy, sz, sw);
    redu[slice][lane] = make_float4(ux, uy, uz, uw);
    __syncthreads();
    float Mx=-1e30f, My=-1e30f, Mz=-1e30f, Mw=-1e30f;
#pragma unroll
    for (int k = 0; k < 16; k++) {
        float4 fm = redm[k][lane];
        Mx = fmaxf(Mx, fm.x); My = fmaxf(My, fm.y);
        Mz = fmaxf(Mz, fm.z); Mw = fmaxf(Mw, fm.w);
    }
    float Sx=0.f, Sy=0.f, Sz=0.f, Sw=0.f;
    float Ux=0.f, Uy=0.f, Uz=0.f, Uw=0.f;
#pragma unroll
    for (int k = 0; k < 16; k++) {
        float4 fm = redm[k][lane];
        float4 fs = reds[k][lane];
        float4 fu = redu[k][lane];
        float ex = __expf(fm.x - Mx), ey = __expf(fm.y - My);
        float ez = __expf(fm.z - Mz), ew = __expf(fm.w - Mw);
        Sx += fs.x * ex; Sy += fs.y * ey; Sz += fs.z * ez; Sw += fs.w * ew;
        Ux = fmaxf(Ux, fu.x * ex); Uy = fmaxf(Uy, fu.y * ey);
        Uz = fmaxf(Uz, fu.z * ez); Uw = fmaxf(Uw, fu.w * ew);
    }
    const float ivx = 1.f / Sx, ivy = 1.f / Sy, ivz = 1.f / Sz, ivw = 1.f / Sw;
    const float tux = Ux * 0.1f, tuy = Uy * 0.1f, tuz = Uz * 0.1f, tuw = Uw * 0.1f;

    float cx=0.f, cy=0.f, cz2=0.f, cw=0.f;
#pragma unroll 4
    for (int n = n0; n < n1; n++) {
        float4 x  = LG[lgbase + (long long)n * 128];
        float4 sm = SM[lgbase + (long long)n * 128];
        float ex = __expf(x.x - Mx), ey = __expf(x.y - My);
        float ez = __expf(x.z - Mz), ew = __expf(x.w - Mw);
        float uxx = sm.x * ex, uyy = sm.y * ey, uzz = sm.z * ez, uww = sm.w * ew;
        float tx = (fabsf(uxx) >= tux) ? uxx * ivx : 0.f;
        float ty = (fabsf(uyy) >= tuy) ? uyy * ivy : 0.f;
        float tz = (fabsf(uzz) >= tuz) ? uzz * ivz : 0.f;
        float tw = (fabsf(uww) >= tuw) ? uww * ivw : 0.f;
        TMP[tmpbase + (long long)(n - 1) * 128] = make_float4(tx, ty, tz, tw);
        cx += tx; cy += ty; cz2 += tz; cw += tw;
    }
    redm[slice][lane] = make_float4(cx, cy, cz2, cw);
    __syncthreads();
    if (slice == 0) {
        float4 tot = make_float4(0.f, 0.f, 0.f, 0.f);
#pragma unroll
        for (int k = 0; k < 16; k++) {
            float4 f = redm[k][lane];
            tot.x += f.x; tot.y += f.y; tot.z += f.z; tot.w += f.w;
        }
        ((float4*)outp)[(long long)b * 128 + cb * 32 + lane] = tot;
    }
}

// ---------------------------------------------------------------------------
extern "C" void kernel_launch(void* const* d_in, const int* in_sizes, int n_in,
                              void* d_out, int out_size)
{
    const float* node  = (const float*)d_in[0];
    const float* edge  = (const float*)d_in[1];
    const float* emb1  = (const float*)d_in[2];
    const float* emb2  = (const float*)d_in[3];
    const float* Wq_w  = (const float*)d_in[4];
    const float* Wq_b  = (const float*)d_in[5];
    const float* Wk_w  = (const float*)d_in[6];
    const float* Wk_b  = (const float*)d_in[7];
    const float* Wew_w = (const float*)d_in[8];
    const float* Wa_w1 = (const float*)d_in[9];
    const float* Wa_w2 = (const float*)d_in[10];
    const float* nt_w  = (const float*)d_in[11];
    const float* nt_b  = (const float*)d_in[12];
    const float* et_w1 = (const float*)d_in[13];
    const float* et_b1 = (const float*)d_in[14];
    const float* et_w2 = (const float*)d_in[15];
    const float* et_b2 = (const float*)d_in[16];

    float* outp  = (float*)d_out;            // (B, IN) first
    float* d_tmp = outp + Bb * INc;          // then (B, N-1, IN)

    void *pSum, *pLG, *pH12, *pQK, *pBeff, *pBsum;
    void *pWeH, *pWsH, *pWsL, *pWa2H;
    cudaGetSymbolAddress(&pSum,  g_sum);
    cudaGetSymbolAddress(&pLG,   g_logits);
    cudaGetSymbolAddress(&pH12,  g_H12);
    cudaGetSymbolAddress(&pQK,   g_QK);
    cudaGetSymbolAddress(&pBeff, g_beff);
    cudaGetSymbolAddress(&pBsum, g_bsum);
    cudaGetSymbolAddress(&pWeH,  g_WeffH);
    cudaGetSymbolAddress(&pWsH,  g_WsumH);
    cudaGetSymbolAddress(&pWsL,  g_WsumL);
    cudaGetSymbolAddress(&pWa2H, g_Wa2H);

    // dynamic smem limits (idempotent host calls; no allocation)
    cudaFuncSetAttribute(mma_gemm<64, 2, false>,  cudaFuncAttributeMaxDynamicSharedMemorySize, 51200);
    cudaFuncSetAttribute(mma_gemm<128, 2, false>, cudaFuncAttributeMaxDynamicSharedMemorySize, 61440);
    cudaFuncSetAttribute(mma_gemm<128, 3, false>, cudaFuncAttributeMaxDynamicSharedMemorySize, 81920);

    // weight prep (tiny, one-time per launch)
    tofp16<<<16, 256>>>(Wa_w2, (__half*)pWa2H, 512 * 64);
    prepsum<<<512, 256>>>(nt_w, nt_b, et_w2, et_b2);

    // Q -> Weff/beff -> QK (batched N=64 GEMM, K=512, 2-term)
    q_kernel<<<dim3(Bb, 8), 256>>>(node, Wq_w, Wq_b);
    weff_kernel<<<dim3(Bb, 8), 256>>>(Wk_w, Wk_b);
    mma_gemm<64, 2, false><<<dim3(1, Nn / 128, Bb), 256, 51200>>>(
        node, Cc, Cc, nullptr, 0, 0,
        (const __half*)pWeH, nullptr, (const float*)pBeff, (float*)pQK, 64,
        (long long)Nn * Cc, 64LL * 512, 64LL, (long long)Nn * 64);

    // fused val + H12 (replaces val_kernel + H12 GEMM)
    val_h12_kernel<<<Mtot / 8, 256>>>(edge, emb1, emb2, Wew_w, Wa_w1, et_w1, et_b1);

    // logits = H1 @ Wa_w2^T           (M x 512, K=64, 2-term)
    mma_gemm<128, 2, false><<<dim3(4, Mtot / 128, 1), 256, 61440>>>(
        (const float*)pH12, 128, 64, nullptr, 0, 0,
        (const __half*)pWa2H, nullptr, nullptr, (float*)pLG, INc, 0, 0, 0, 0);

    // sum = node @ nt_w^T + H2 @ et_w2^T + (nt_b + et_b2)  (K=576, 3-term)
    mma_gemm<128, 3, false><<<dim3(4, Mtot / 128, 1), 256, 81920>>>(
        node, Cc, Cc, (const float*)pH12 + 64, 128, 64,
        (const __half*)pWsH, (const __half*)pWsL, (const float*)pBsum,
        (float*)pSum, INc, 0, 0, 0, 0);

    // fused softmax + combine + threshold + mask + colsum
    tail_kernel<<<dim3(4, Bb), 512>>>(d_tmp, outp);
}

// round 13
// speedup vs baseline: 1.1642x; 1.0365x over previous
#include <cuda_runtime.h>
#include <cuda_fp16.h>
#include <math.h>
#include <stdint.h>

#define Bb   64
#define Nn   2048
#define Cc   512
#define Ee   32
#define Ac   8
#define INc  512
#define Hc   64
#define Mtot (Bb*Nn)

// -------------------- device scratch (static; allocation-free) -------------
__device__ float  g_sum    [(long long)Mtot*INc];
__device__ float  g_logits [(long long)Mtot*INc];
__device__ float  g_H12    [(long long)Mtot*128];   // [H1 | H2] fp32
__device__ float  g_QK     [(long long)Mtot*64];
__device__ float  g_Q      [Bb*512];
__device__ float  g_beff   [Bb*64];
__device__ float  g_bsum   [512];
__device__ __half g_WeffH  [Bb*64*512];
__device__ __half g_WsumH  [512*576];
__device__ __half g_WsumL  [512*576];
__device__ __half g_Wa2H   [512*64];

// ========================== helpers ========================================
__device__ __forceinline__ uint32_t smem_u32(const void* p) {
    uint32_t a;
    asm("{ .reg .u64 t; cvta.to.shared.u64 t, %1; cvt.u32.u64 %0, t; }" : "=r"(a) : "l"(p));
    return a;
}
// 8 fp32 -> hi f16x8 (16B at addr), lo f16x8 (16B at addr+lo_off)
__device__ __forceinline__ void split8h(uint32_t addr, uint32_t lo_off, float4 a0, float4 a1) {
    __half2 h0 = __floats2half2_rn(a0.x, a0.y);
    __half2 h1 = __floats2half2_rn(a0.z, a0.w);
    __half2 h2 = __floats2half2_rn(a1.x, a1.y);
    __half2 h3 = __floats2half2_rn(a1.z, a1.w);
    float2 f0 = __half22float2(h0), f1 = __half22float2(h1);
    float2 f2 = __half22float2(h2), f3 = __half22float2(h3);
    __half2 l0 = __floats2half2_rn(a0.x - f0.x, a0.y - f0.y);
    __half2 l1 = __floats2half2_rn(a0.z - f1.x, a0.w - f1.y);
    __half2 l2 = __floats2half2_rn(a1.x - f2.x, a1.y - f2.y);
    __half2 l3 = __floats2half2_rn(a1.z - f3.x, a1.w - f3.y);
    asm volatile("st.shared.v4.b32 [%0], {%1,%2,%3,%4};"
        :: "r"(addr), "r"(*(uint32_t*)&h0), "r"(*(uint32_t*)&h1), "r"(*(uint32_t*)&h2), "r"(*(uint32_t*)&h3));
    asm volatile("st.shared.v4.b32 [%0], {%1,%2,%3,%4};"
        :: "r"(addr + lo_off), "r"(*(uint32_t*)&l0), "r"(*(uint32_t*)&l1), "r"(*(uint32_t*)&l2), "r"(*(uint32_t*)&l3));
}
#define LDSM_X4(r0, r1, r2, r3, addr) \
    asm volatile("ldmatrix.sync.aligned.m8n8.x4.shared.b16 {%0,%1,%2,%3}, [%4];" \
        : "=r"(r0), "=r"(r1), "=r"(r2), "=r"(r3) : "r"(addr))
__device__ __forceinline__ void mma16816h(float d[4], const uint32_t a[4], const uint32_t b[2]) {
    asm volatile("mma.sync.aligned.m16n8k16.row.col.f32.f16.f16.f32 "
        "{%0,%1,%2,%3},{%4,%5,%6,%7},{%8,%9},{%0,%1,%2,%3};"
        : "+f"(d[0]), "+f"(d[1]), "+f"(d[2]), "+f"(d[3])
        : "r"(a[0]), "r"(a[1]), "r"(a[2]), "r"(a[3]), "r"(b[0]), "r"(b[1]));
}
#define STS128(addr, v) \
    asm volatile("st.shared.v4.b32 [%0], {%1,%2,%3,%4};" \
        :: "r"(addr), "r"((v).x), "r"((v).y), "r"((v).z), "r"((v).w))

// ===== mixed-term GEMM, double-buffered smem (1 sync per chunk) =============
// TERMS==2: W single fp16 plane; MMAs = Ah*Wh + Al*Wh.
// TERMS==3: W fp16 hi/lo planes;  MMAs = Ah*Wh + Al*Wh + Ah*Wl.
// C = A(MxK) W(NxK)^T + bias; A = A1 (lda1,K1) concat A2 (lda2,K2), fp32.
template<int NT, int TERMS, bool GELU>
__global__ __launch_bounds__(256, 2)
void mma_gemm(const float* __restrict__ A1, int lda1, int K1,
              const float* __restrict__ A2, int lda2, int K2,
              const __half* __restrict__ Wh, const __half* __restrict__ Wl,
              const float* __restrict__ bias,
              float* __restrict__ C, int ldc,
              long long az, long long wz, long long bz, long long cz)
{
    constexpr uint32_t BLO = NT * 80;                  // B lo-plane offset
    constexpr int NBPL = (TERMS == 3) ? 2 : 1;
    constexpr uint32_t BUFSZ = 2 * 10240 + NBPL * NT * 80;
    extern __shared__ __align__(128) uint8_t smem_dyn[];
    const uint32_t SA = smem_u32(smem_dyn);            // A hi; lo at +10240
    const uint32_t SB = SA + 20480;
    const int Kt = K1 + K2;
    const int tid = threadIdx.x;
    const int wid = tid >> 5, lid = tid & 31;
    const int warp_m = wid & 3, warp_n = wid >> 2;
    const long long row0 = (long long)blockIdx.y * 128;
    const int col0 = blockIdx.x * NT;
    const int z = blockIdx.z;
    const float*  A1z = A1 + (long long)z * az;
    const __half* Whz = Wh + (long long)z * wz;
    float* Cz = C + (long long)z * cz;

    const int lr = tid >> 1, kh = tid & 1;
    const uint32_t sAst = SA + (uint32_t)lr * 80 + (uint32_t)kh * 32;
    const uint32_t sBst = SB + (uint32_t)lr * 80 + (uint32_t)kh * 32;
    const bool bvalid = lr < NT;
    const long long boffg = (long long)(col0 + lr) * Kt + kh * 16;

    uint32_t aoff[2];
#pragma unroll
    for (int mt = 0; mt < 2; mt++) {
        int rowm = warp_m * 32 + mt * 16 + (lid & 7) + ((lid >> 3) & 1) * 8;
        aoff[mt] = SA + (uint32_t)rowm * 80 + (uint32_t)((lid >> 4) & 1) * 16;
    }
    constexpr int NTP = NT / 32;
    uint32_t boff[NTP];
#pragma unroll
    for (int ntp = 0; ntp < NTP; ntp++) {
        int rown = warp_n * (NT / 2) + ntp * 16 + (lid & 7) + ((lid >> 4) & 1) * 8;
        boff[ntp] = SB + (uint32_t)rown * 80 + (uint32_t)((lid >> 3) & 1) * 16;
    }

    float acc[2][NT / 16][4];
#pragma unroll
    for (int i = 0; i < 2; i++)
#pragma unroll
        for (int j = 0; j < NT / 16; j++)
#pragma unroll
            for (int q = 0; q < 4; q++) acc[i][j][q] = 0.f;

    const int nchunk = Kt >> 5;

    // prefetch chunk 0
    float4 a00, a01, a10, a11;
    uint4 pb0, pb1, pbl0, pbl1;
    {
        const float* Arow = A1z + (row0 + lr) * (long long)lda1 + kh * 16;
        a00 = *(const float4*)(Arow);
        a01 = *(const float4*)(Arow + 4);
        a10 = *(const float4*)(Arow + 8);
        a11 = *(const float4*)(Arow + 12);
        if (bvalid) {
            pb0 = *(const uint4*)(Whz + boffg);
            pb1 = *(const uint4*)(Whz + boffg + 8);
            if (TERMS == 3) {
                pbl0 = *(const uint4*)(Wl + boffg);
                pbl1 = *(const uint4*)(Wl + boffg + 8);
            }
        }
    }

    for (int ch = 0; ch < nchunk; ch++) {
        const uint32_t bo = (uint32_t)(ch & 1) * BUFSZ;
        split8h(sAst + bo,      10240, a00, a01);
        split8h(sAst + bo + 16, 10240, a10, a11);
        if (bvalid) {
            STS128(sBst + bo,      pb0);
            STS128(sBst + bo + 16, pb1);
            if (TERMS == 3) {
                STS128(sBst + bo + BLO,      pbl0);
                STS128(sBst + bo + BLO + 16, pbl1);
            }
        }
        __syncthreads();

        if (ch + 1 < nchunk) {
            const int k0 = (ch + 1) * 32;
            const float* Arow = (k0 < K1)
                ? A1z + (row0 + lr) * (long long)lda1 + k0 + kh * 16
                : A2  + (row0 + lr) * (long long)lda2 + (k0 - K1) + kh * 16;
            a00 = *(const float4*)(Arow);
            a01 = *(const float4*)(Arow + 4);
            a10 = *(const float4*)(Arow + 8);
            a11 = *(const float4*)(Arow + 12);
            if (bvalid) {
                pb0 = *(const uint4*)(Whz + boffg + k0);
                pb1 = *(const uint4*)(Whz + boffg + k0 + 8);
                if (TERMS == 3) {
                    pbl0 = *(const uint4*)(Wl + boffg + k0);
                    pbl1 = *(const uint4*)(Wl + boffg + k0 + 8);
                }
            }
        }

#pragma unroll
        for (int khalf = 0; khalf < 2; khalf++) {
            const uint32_t kb = (uint32_t)khalf * 32 + bo;
            uint32_t Ah[2][4], Al[2][4];
#pragma unroll
            for (int mt = 0; mt < 2; mt++) {
                LDSM_X4(Ah[mt][0], Ah[mt][1], Ah[mt][2], Ah[mt][3], aoff[mt] + kb);
                LDSM_X4(Al[mt][0], Al[mt][1], Al[mt][2], Al[mt][3], aoff[mt] + kb + 10240);
            }
#pragma unroll
            for (int ntp = 0; ntp < NTP; ntp++) {
                uint32_t Bh[4], Bl[4];
                LDSM_X4(Bh[0], Bh[1], Bh[2], Bh[3], boff[ntp] + kb);
                if (TERMS == 3)
                    LDSM_X4(Bl[0], Bl[1], Bl[2], Bl[3], boff[ntp] + kb + BLO);
#pragma unroll
                for (int mt = 0; mt < 2; mt++) {
#pragma unroll
                    for (int nt2 = 0; nt2 < 2; nt2++) {
                        float* d = acc[mt][ntp * 2 + nt2];
                        mma16816h(d, Ah[mt], &Bh[nt2 * 2]);       // hi*Whi
                        mma16816h(d, Al[mt], &Bh[nt2 * 2]);       // lo*Whi
                        if (TERMS == 3)
                            mma16816h(d, Ah[mt], &Bl[nt2 * 2]);   // hi*Wlo
                    }
                }
            }
        }
    }

    const int g = lid >> 2, t = lid & 3;
    const float* biz = bias ? bias + (long long)z * bz : nullptr;
#pragma unroll
    for (int mt = 0; mt < 2; mt++) {
        long long rA = row0 + warp_m * 32 + mt * 16 + g;
        long long rB = rA + 8;
#pragma unroll
        for (int nt = 0; nt < NT / 16; nt++) {
            int col = col0 + warp_n * (NT / 2) + nt * 8 + 2 * t;
            float b0 = biz ? biz[col] : 0.f;
            float b1 = biz ? biz[col + 1] : 0.f;
            float* d = acc[mt][nt];
            float o0 = d[0] + b0, o1 = d[1] + b1, o2 = d[2] + b0, o3 = d[3] + b1;
            if (GELU) {
                o0 = 0.5f * o0 * (1.f + erff(o0 * 0.70710678118654752f));
                o1 = 0.5f * o1 * (1.f + erff(o1 * 0.70710678118654752f));
                o2 = 0.5f * o2 * (1.f + erff(o2 * 0.70710678118654752f));
                o3 = 0.5f * o3 * (1.f + erff(o3 * 0.70710678118654752f));
            }
            *(float2*)(Cz + rA * ldc + col) = make_float2(o0, o1);
            *(float2*)(Cz + rB * ldc + col) = make_float2(o2, o3);
        }
    }
}

// -------------------- fp32 -> fp16 (round) ---------------------------------
__global__ __launch_bounds__(256)
void tofp16(const float* __restrict__ s, __half* __restrict__ d, int n)
{
    int i = (blockIdx.x * 256 + threadIdx.x) * 8;
    if (i >= n) return;
    float4 a = *(const float4*)(s + i);
    float4 b = *(const float4*)(s + i + 4);
    __half2 h0 = __floats2half2_rn(a.x, a.y), h1 = __floats2half2_rn(a.z, a.w);
    __half2 h2 = __floats2half2_rn(b.x, b.y), h3 = __floats2half2_rn(b.z, b.w);
    *(uint4*)(d + i) = make_uint4(*(uint32_t*)&h0, *(uint32_t*)&h1, *(uint32_t*)&h2, *(uint32_t*)&h3);
}

// ---- Q = node[:, 0, :] @ Wq_w^T + Wq_b; grid (Bb, 8), 4 thr/output --------
__global__ __launch_bounds__(256)
void q_kernel(const float* __restrict__ node, const float* __restrict__ Wq_w,
              const float* __restrict__ Wq_b)
{
    __shared__ __align__(16) float xs[512];
    const int b = blockIdx.x, part = blockIdx.y, tid = threadIdx.x;
    const float* xr = node + (long long)b * Nn * Cc;
    xs[tid]       = xr[tid];
    xs[tid + 256] = xr[tid + 256];
    __syncthreads();
    const int jj = tid >> 2;        // 0..63
    const int t4 = tid & 3;         // k-quarter
    const int j = part * 64 + jj;
    const float4* x4 = (const float4*)xs + t4 * 32;
    const float4* w4 = (const float4*)(Wq_w + (long long)j * 512) + t4 * 32;
    float acc0 = 0.f, acc1 = 0.f;
#pragma unroll 8
    for (int k = 0; k < 32; k += 2) {
        float4 w0 = w4[k], x0 = x4[k];
        float4 w1 = w4[k + 1], x1 = x4[k + 1];
        acc0 += w0.x*x0.x + w0.y*x0.y + w0.z*x0.z + w0.w*x0.w;
        acc1 += w1.x*x1.x + w1.y*x1.y + w1.z*x1.z + w1.w*x1.w;
    }
    float acc = acc0 + acc1;
    acc += __shfl_xor_sync(0xffffffffu, acc, 1);
    acc += __shfl_xor_sync(0xffffffffu, acc, 2);
    if (t4 == 0) g_Q[b * 512 + j] = acc + Wq_b[j];
}

// ------ Weff[b,e2,:] = sum_a Q[b,a,e2] * Wk_w[a*64+e2,:] -> fp16 -----------
__global__ __launch_bounds__(256)
void weff_kernel(const float* __restrict__ Wk_w, const float* __restrict__ Wk_b)
{
    __shared__ float Qs[512];
    const int b = blockIdx.x, part = blockIdx.y, tid = threadIdx.x;
    Qs[tid]       = g_Q[b * 512 + tid];
    Qs[tid + 256] = g_Q[b * 512 + 256 + tid];
    __syncthreads();
    const int i0 = part * 4096;
    for (int idx = i0 + tid; idx < i0 + 4096; idx += 256) {
        int e2 = idx >> 9, c = idx & 511;
        float acc = 0.f;
#pragma unroll
        for (int a = 0; a < 8; a++)
            acc += Qs[a * 64 + e2] * Wk_w[(long long)(a * 64 + e2) * 512 + c];
        g_WeffH[(long long)b * 32768 + idx] = __float2half_rn(acc);
    }
    if (part == 0 && tid < 64) {
        float acc = 0.f;
#pragma unroll
        for (int a = 0; a < 8; a++) acc += Qs[a * 64 + tid] * Wk_b[a * 64 + tid];
        g_beff[b * 64 + tid] = acc;
    }
}

// -------------------- weight prep ------------------------------------------
__global__ void prepsum(const float* __restrict__ nt_w, const float* __restrict__ nt_b,
                        const float* __restrict__ et_w2, const float* __restrict__ et_b2)
{
    int n = blockIdx.x, t = threadIdx.x;
    for (int k = t; k < 576; k += 256) {
        float v = (k < 512) ? nt_w[n * 512 + k] : et_w2[n * 64 + (k - 512)];
        __half hh = __float2half_rn(v);
        g_WsumH[n * 576 + k] = hh;
        g_WsumL[n * 576 + k] = __float2half_rn(v - __half2float(hh));
    }
    if (t == 0) g_bsum[n] = nt_b[n] + et_b2[n];
}

// ---- fused val + H12, 32 rows per block (weights amortized 4x) ------------
// val = selu(rho(QKlo*ew) + QKhi*emb1 + emb2); H12 = gelu(val @ W12^T + b12)
__global__ __launch_bounds__(256)
void val_h12_kernel(const float* __restrict__ edge, const float* __restrict__ emb1,
                    const float* __restrict__ emb2, const float* __restrict__ Wew,
                    const float* __restrict__ Wa_w1, const float* __restrict__ et_w1,
                    const float* __restrict__ et_b1)
{
    __shared__ float WewT[32 * 32];      // [j][e]
    __shared__ float er[32][32];
    __shared__ float vs[32][33];         // padded
    __shared__ float W12T[32][132];      // [e][h], padded
    __shared__ float b12s[128];
    const int tid = threadIdx.x;
    const long long row0 = (long long)blockIdx.x * 32;
    for (int i = tid; i < 1024; i += 256) WewT[(i & 31) * 32 + (i >> 5)] = Wew[i];
    for (int i = tid; i < 1024; i += 256) er[i >> 5][i & 31] = edge[row0 * 32 + i];
    for (int i = tid; i < 4096; i += 256) {
        int h = i >> 5, e = i & 31;
        W12T[e][h] = (h < 64) ? Wa_w1[h * 32 + e] : et_w1[(h - 64) * 32 + e];
    }
    if (tid < 128) b12s[tid] = (tid < 64) ? 0.f : et_b1[tid - 64];
    __syncthreads();

    // phase 1: val for 32 rows (4 per thread)
    {
        const int rb = tid >> 5, e = tid & 31;
        const float sc = 1.0507009873554805f, al = 1.6732632423543772f;
#pragma unroll
        for (int q = 0; q < 4; q++) {
            const int r = q * 8 + rb;
            const long long row = row0 + r;
            float ew = 0.f;
#pragma unroll
            for (int j = 0; j < 32; j++) ew += er[r][j] * WewT[j * 32 + e];
            float qk  = g_QK[row * 64 + e];
            float qkh = g_QK[row * 64 + 32 + e];
            float x = qk * ew;
            float rr = (x > 0.f) ? sqrtf(x) : -sqrtf(-x);
            float v = rr + qkh * emb1[row * 32 + e] + emb2[row * 32 + e];
            vs[r][e] = (v > 0.f) ? sc * v : sc * al * (expf(v) - 1.f);
        }
    }
    __syncthreads();

    // phase 2: H12 for 32 rows (16 per thread, 2-row ILP)
    const int h = tid & 127, half = tid >> 7;
    float w[32];
#pragma unroll
    for (int e = 0; e < 32; e++) w[e] = W12T[e][h];
    const float bb = b12s[h];
#pragma unroll
    for (int rp = 0; rp < 8; rp++) {
        const int r0 = half * 16 + rp * 2;
        float acc0 = bb, acc1 = bb;
#pragma unroll
        for (int e = 0; e < 32; e++) {
            acc0 = fmaf(vs[r0][e],     w[e], acc0);
            acc1 = fmaf(vs[r0 + 1][e], w[e], acc1);
        }
        float g0 = 0.5f * acc0 * (1.f + erff(acc0 * 0.70710678118654752f));
        float g1 = 0.5f * acc1 * (1.f + erff(acc1 * 0.70710678118654752f));
        g_H12[(row0 + r0) * 128 + h]     = g0;
        g_H12[(row0 + r0 + 1) * 128 + h] = g1;
    }
}

// ---- fused tail: 2 passes, __expf, single tmp write ------------------------
__global__ __launch_bounds__(512)
void tail_kernel(float* __restrict__ d_tmp, float* __restrict__ outp)
{
    __shared__ float4 redm[16][32];
    __shared__ float4 reds[16][32];
    __shared__ float4 redu[16][32];
    const int b = blockIdx.y, cb = blockIdx.x;
    const int slice = threadIdx.x >> 5, lane = threadIdx.x & 31;
    const long long lgbase  = (long long)b * 2048 * 128 + cb * 32 + lane;
    const long long tmpbase = (long long)b * 2047 * 128 + cb * 32 + lane;
    const float4* LG = (const float4*)g_logits;
    const float4* SM = (const float4*)g_sum;
    float4* TMP = (float4*)d_tmp;
    const int n0 = 1 + slice * 128;
    const int n1 = min(2048, n0 + 128);

    float mx=-1e30f, my=-1e30f, mz=-1e30f, mw=-1e30f;
    float sx=0.f, sy=0.f, sz=0.f, sw=0.f;
    float ux=0.f, uy=0.f, uz=0.f, uw=0.f;
#pragma unroll 4
    for (int n = n0; n < n1; n++) {
        float4 x  = LG[lgbase + (long long)n * 128];
        float4 sm = SM[lgbase + (long long)n * 128];
        if (x.x > mx) { float f = __expf(mx - x.x); sx = sx * f + 1.f; ux = fmaxf(ux * f, fabsf(sm.x)); mx = x.x; }
        else          { float e = __expf(x.x - mx); sx += e; ux = fmaxf(ux, fabsf(sm.x) * e); }
        if (x.y > my) { float f = __expf(my - x.y); sy = sy * f + 1.f; uy = fmaxf(uy * f, fabsf(sm.y)); my = x.y; }
        else          { float e = __expf(x.y - my); sy += e; uy = fmaxf(uy, fabsf(sm.y) * e); }
        if (x.z > mz) { float f = __expf(mz - x.z); sz = sz * f + 1.f; uz = fmaxf(uz * f, fabsf(sm.z)); mz = x.z; }
        else          { float e = __expf(x.z - mz); sz += e; uz = fmaxf(uz, fabsf(sm.z) * e); }
        if (x.w > mw) { float f = __expf(mw - x.w); sw = sw * f + 1.f; uw = fmaxf(uw * f, fabsf(sm.w)); mw = x.w; }
        else          { float e = __expf(x.w - mw); sw += e; uw = fmaxf(uw, fabsf(sm.w) * e); }
    }
    redm[slice][lane] = make_float4(mx, my, mz, mw);
    reds[slice][lane] = make_float4(sx, sy, sz, sw);
    redu[slice][lane] = make_float4(ux, uy, uz, uw);
    __syncthreads();
    float Mx=-1e30f, My=-1e30f, Mz=-1e30f, Mw=-1e30f;
#pragma unroll
    for (int k = 0; k < 16; k++) {
        float4 fm = redm[k][lane];
        Mx = fmaxf(Mx, fm.x); My = fmaxf(My, fm.y);
        Mz = fmaxf(Mz, fm.z); Mw = fmaxf(Mw, fm.w);
    }
    float Sx=0.f, Sy=0.f, Sz=0.f, Sw=0.f;
    float Ux=0.f, Uy=0.f, Uz=0.f, Uw=0.f;
#pragma unroll
    for (int k = 0; k < 16; k++) {
        float4 fm = redm[k][lane];
        float4 fs = reds[k][lane];
        float4 fu = redu[k][lane];
        float ex = __expf(fm.x - Mx), ey = __expf(fm.y - My);
        float ez = __expf(fm.z - Mz), ew = __expf(fm.w - Mw);
        Sx += fs.x * ex; Sy += fs.y * ey; Sz += fs.z * ez; Sw += fs.w * ew;
        Ux = fmaxf(Ux, fu.x * ex); Uy = fmaxf(Uy, fu.y * ey);
        Uz = fmaxf(Uz, fu.z * ez); Uw = fmaxf(Uw, fu.w * ew);
    }
    const float ivx = 1.f / Sx, ivy = 1.f / Sy, ivz = 1.f / Sz, ivw = 1.f / Sw;
    const float tux = Ux * 0.1f, tuy = Uy * 0.1f, tuz = Uz * 0.1f, tuw = Uw * 0.1f;

    float cx=0.f, cy=0.f, cz2=0.f, cw=0.f;
#pragma unroll 4
    for (int n = n0; n < n1; n++) {
        float4 x  = LG[lgbase + (long long)n * 128];
        float4 sm = SM[lgbase + (long long)n * 128];
        float ex = __expf(x.x - Mx), ey = __expf(x.y - My);
        float ez = __expf(x.z - Mz), ew = __expf(x.w - Mw);
        float uxx = sm.x * ex, uyy = sm.y * ey, uzz = sm.z * ez, uww = sm.w * ew;
        float tx = (fabsf(uxx) >= tux) ? uxx * ivx : 0.f;
        float ty = (fabsf(uyy) >= tuy) ? uyy * ivy : 0.f;
        float tz = (fabsf(uzz) >= tuz) ? uzz * ivz : 0.f;
        float tw = (fabsf(uww) >= tuw) ? uww * ivw : 0.f;
        TMP[tmpbase + (long long)(n - 1) * 128] = make_float4(tx, ty, tz, tw);
        cx += tx; cy += ty; cz2 += tz; cw += tw;
    }
    redm[slice][lane] = make_float4(cx, cy, cz2, cw);
    __syncthreads();
    if (slice == 0) {
        float4 tot = make_float4(0.f, 0.f, 0.f, 0.f);
#pragma unroll
        for (int k = 0; k < 16; k++) {
            float4 f = redm[k][lane];
            tot.x += f.x; tot.y += f.y; tot.z += f.z; tot.w += f.w;
        }
        ((float4*)outp)[(long long)b * 128 + cb * 32 + lane] = tot;
    }
}

// ---------------------------------------------------------------------------
extern "C" void kernel_launch(void* const* d_in, const int* in_sizes, int n_in,
                              void* d_out, int out_size)
{
    const float* node  = (const float*)d_in[0];
    const float* edge  = (const float*)d_in[1];
    const float* emb1  = (const float*)d_in[2];
    const float* emb2  = (const float*)d_in[3];
    const float* Wq_w  = (const float*)d_in[4];
    const float* Wq_b  = (const float*)d_in[5];
    const float* Wk_w  = (const float*)d_in[6];
    const float* Wk_b  = (const float*)d_in[7];
    const float* Wew_w = (const float*)d_in[8];
    const float* Wa_w1 = (const float*)d_in[9];
    const float* Wa_w2 = (const float*)d_in[10];
    const float* nt_w  = (const float*)d_in[11];
    const float* nt_b  = (const float*)d_in[12];
    const float* et_w1 = (const float*)d_in[13];
    const float* et_b1 = (const float*)d_in[14];
    const float* et_w2 = (const float*)d_in[15];
    const float* et_b2 = (const float*)d_in[16];

    float* outp  = (float*)d_out;            // (B, IN) first
    float* d_tmp = outp + Bb * INc;          // then (B, N-1, IN)

    void *pSum, *pLG, *pH12, *pQK, *pBeff, *pBsum;
    void *pWeH, *pWsH, *pWsL, *pWa2H;
    cudaGetSymbolAddress(&pSum,  g_sum);
    cudaGetSymbolAddress(&pLG,   g_logits);
    cudaGetSymbolAddress(&pH12,  g_H12);
    cudaGetSymbolAddress(&pQK,   g_QK);
    cudaGetSymbolAddress(&pBeff, g_beff);
    cudaGetSymbolAddress(&pBsum, g_bsum);
    cudaGetSymbolAddress(&pWeH,  g_WeffH);
    cudaGetSymbolAddress(&pWsH,  g_WsumH);
    cudaGetSymbolAddress(&pWsL,  g_WsumL);
    cudaGetSymbolAddress(&pWa2H, g_Wa2H);

    // dynamic smem limits (idempotent host calls; no allocation)
    cudaFuncSetAttribute(mma_gemm<64, 2, false>,  cudaFuncAttributeMaxDynamicSharedMemorySize, 51200);
    cudaFuncSetAttribute(mma_gemm<128, 2, false>, cudaFuncAttributeMaxDynamicSharedMemorySize, 61440);
    cudaFuncSetAttribute(mma_gemm<128, 3, false>, cudaFuncAttributeMaxDynamicSharedMemorySize, 81920);

    // weight prep (tiny, one-time per launch)
    tofp16<<<16, 256>>>(Wa_w2, (__half*)pWa2H, 512 * 64);
    prepsum<<<512, 256>>>(nt_w, nt_b, et_w2, et_b2);

    // Q -> Weff/beff -> QK (batched N=64 GEMM, K=512, 2-term)
    q_kernel<<<dim3(Bb, 8), 256>>>(node, Wq_w, Wq_b);
    weff_kernel<<<dim3(Bb, 8), 256>>>(Wk_w, Wk_b);
    mma_gemm<64, 2, false><<<dim3(1, Nn / 128, Bb), 256, 51200>>>(
        node, Cc, Cc, nullptr, 0, 0,
        (const __half*)pWeH, nullptr, (const float*)pBeff, (float*)pQK, 64,
        (long long)Nn * Cc, 64LL * 512, 64LL, (long long)Nn * 64);

    // fused val + H12 (32 rows/block)
    val_h12_kernel<<<Mtot / 32, 256>>>(edge, emb1, emb2, Wew_w, Wa_w1, et_w1, et_b1);

    // logits = H1 @ Wa_w2^T           (M x 512, K=64, 2-term)
    mma_gemm<128, 2, false><<<dim3(4, Mtot / 128, 1), 256, 61440>>>(
        (const float*)pH12, 128, 64, nullptr, 0, 0,
        (const __half*)pWa2H, nullptr, nullptr, (float*)pLG, INc, 0, 0, 0, 0);

    // sum = node @ nt_w^T + H2 @ et_w2^T + (nt_b + et_b2)  (K=576, 3-term)
    mma_gemm<128, 3, false><<<dim3(4, Mtot / 128, 1), 256, 81920>>>(
        node, Cc, Cc, (const float*)pH12 + 64, 128, 64,
        (const __half*)pWsH, (const __half*)pWsL, (const float*)pBsum,
        (float*)pSum, INc, 0, 0, 0, 0);

    // fused softmax + combine + threshold + mask + colsum
    tail_kernel<<<dim3(4, Bb), 512>>>(d_tmp, outp);
}

// round 14
// speedup vs baseline: 1.3505x; 1.1600x over previous
#include <cuda_runtime.h>
#include <cuda_fp16.h>
#include <math.h>
#include <stdint.h>

#define Bb   64
#define Nn   2048
#define Cc   512
#define Ee   32
#define Ac   8
#define INc  512
#define Hc   64
#define Mtot (Bb*Nn)

// -------------------- device scratch (static; allocation-free) -------------
__device__ float  g_sum    [(long long)Mtot*INc];
__device__ __half g_logitsH[(long long)Mtot*INc];
__device__ float  g_H12    [(long long)Mtot*128];   // [H1 | H2] fp32
__device__ float  g_QK     [(long long)Mtot*64];
__device__ float  g_Q      [Bb*512];
__device__ float  g_beff   [Bb*64];
__device__ float  g_bsum   [512];
__device__ __half g_WeffH  [Bb*64*512];
__device__ __half g_WsumH  [512*576];
__device__ __half g_WsumL  [512*576];
__device__ __half g_Wa2H   [512*64];

// ========================== helpers ========================================
__device__ __forceinline__ uint32_t smem_u32(const void* p) {
    uint32_t a;
    asm("{ .reg .u64 t; cvta.to.shared.u64 t, %1; cvt.u32.u64 %0, t; }" : "=r"(a) : "l"(p));
    return a;
}
// 8 fp32 -> hi f16x8 (16B at addr), lo f16x8 (16B at addr+lo_off)
__device__ __forceinline__ void split8h(uint32_t addr, uint32_t lo_off, float4 a0, float4 a1) {
    __half2 h0 = __floats2half2_rn(a0.x, a0.y);
    __half2 h1 = __floats2half2_rn(a0.z, a0.w);
    __half2 h2 = __floats2half2_rn(a1.x, a1.y);
    __half2 h3 = __floats2half2_rn(a1.z, a1.w);
    float2 f0 = __half22float2(h0), f1 = __half22float2(h1);
    float2 f2 = __half22float2(h2), f3 = __half22float2(h3);
    __half2 l0 = __floats2half2_rn(a0.x - f0.x, a0.y - f0.y);
    __half2 l1 = __floats2half2_rn(a0.z - f1.x, a0.w - f1.y);
    __half2 l2 = __floats2half2_rn(a1.x - f2.x, a1.y - f2.y);
    __half2 l3 = __floats2half2_rn(a1.z - f3.x, a1.w - f3.y);
    asm volatile("st.shared.v4.b32 [%0], {%1,%2,%3,%4};"
        :: "r"(addr), "r"(*(uint32_t*)&h0), "r"(*(uint32_t*)&h1), "r"(*(uint32_t*)&h2), "r"(*(uint32_t*)&h3));
    asm volatile("st.shared.v4.b32 [%0], {%1,%2,%3,%4};"
        :: "r"(addr + lo_off), "r"(*(uint32_t*)&l0), "r"(*(uint32_t*)&l1), "r"(*(uint32_t*)&l2), "r"(*(uint32_t*)&l3));
}
#define LDSM_X4(r0, r1, r2, r3, addr) \
    asm volatile("ldmatrix.sync.aligned.m8n8.x4.shared.b16 {%0,%1,%2,%3}, [%4];" \
        : "=r"(r0), "=r"(r1), "=r"(r2), "=r"(r3) : "r"(addr))
__device__ __forceinline__ void mma16816h(float d[4], const uint32_t a[4], const uint32_t b[2]) {
    asm volatile("mma.sync.aligned.m16n8k16.row.col.f32.f16.f16.f32 "
        "{%0,%1,%2,%3},{%4,%5,%6,%7},{%8,%9},{%0,%1,%2,%3};"
        : "+f"(d[0]), "+f"(d[1]), "+f"(d[2]), "+f"(d[3])
        : "r"(a[0]), "r"(a[1]), "r"(a[2]), "r"(a[3]), "r"(b[0]), "r"(b[1]));
}
#define STS128(addr, v) \
    asm volatile("st.shared.v4.b32 [%0], {%1,%2,%3,%4};" \
        :: "r"(addr), "r"((v).x), "r"((v).y), "r"((v).z), "r"((v).w))

// ===== mixed-term GEMM, double-buffered smem (1 sync per chunk) =============
// TERMS==2: W single fp16 plane; MMAs = Ah*Wh + Al*Wh.
// TERMS==3: W fp16 hi/lo planes;  MMAs = Ah*Wh + Al*Wh + Ah*Wl.
// HOUT: store fp16 to Ch instead of fp32 to C.
// C = A(MxK) W(NxK)^T + bias; A = A1 (lda1,K1) concat A2 (lda2,K2), fp32.
template<int NT, int TERMS, bool HOUT>
__global__ __launch_bounds__(256, 2)
void mma_gemm(const float* __restrict__ A1, int lda1, int K1,
              const float* __restrict__ A2, int lda2, int K2,
              const __half* __restrict__ Wh, const __half* __restrict__ Wl,
              const float* __restrict__ bias,
              float* __restrict__ C, __half* __restrict__ Ch, int ldc,
              long long az, long long wz, long long bz, long long cz)
{
    constexpr uint32_t BLO = NT * 80;                  // B lo-plane offset
    constexpr int NBPL = (TERMS == 3) ? 2 : 1;
    constexpr uint32_t BUFSZ = 2 * 10240 + NBPL * NT * 80;
    extern __shared__ __align__(128) uint8_t smem_dyn[];
    const uint32_t SA = smem_u32(smem_dyn);            // A hi; lo at +10240
    const uint32_t SB = SA + 20480;
    const int Kt = K1 + K2;
    const int tid = threadIdx.x;
    const int wid = tid >> 5, lid = tid & 31;
    const int warp_m = wid & 3, warp_n = wid >> 2;
    const long long row0 = (long long)blockIdx.y * 128;
    const int col0 = blockIdx.x * NT;
    const int z = blockIdx.z;
    const float*  A1z = A1 + (long long)z * az;
    const __half* Whz = Wh + (long long)z * wz;

    const int lr = tid >> 1, kh = tid & 1;
    const uint32_t sAst = SA + (uint32_t)lr * 80 + (uint32_t)kh * 32;
    const uint32_t sBst = SB + (uint32_t)lr * 80 + (uint32_t)kh * 32;
    const bool bvalid = lr < NT;
    const long long boffg = (long long)(col0 + lr) * Kt + kh * 16;

    uint32_t aoff[2];
#pragma unroll
    for (int mt = 0; mt < 2; mt++) {
        int rowm = warp_m * 32 + mt * 16 + (lid & 7) + ((lid >> 3) & 1) * 8;
        aoff[mt] = SA + (uint32_t)rowm * 80 + (uint32_t)((lid >> 4) & 1) * 16;
    }
    constexpr int NTP = NT / 32;
    uint32_t boff[NTP];
#pragma unroll
    for (int ntp = 0; ntp < NTP; ntp++) {
        int rown = warp_n * (NT / 2) + ntp * 16 + (lid & 7) + ((lid >> 4) & 1) * 8;
        boff[ntp] = SB + (uint32_t)rown * 80 + (uint32_t)((lid >> 3) & 1) * 16;
    }

    float acc[2][NT / 16][4];
#pragma unroll
    for (int i = 0; i < 2; i++)
#pragma unroll
        for (int j = 0; j < NT / 16; j++)
#pragma unroll
            for (int q = 0; q < 4; q++) acc[i][j][q] = 0.f;

    const int nchunk = Kt >> 5;

    // prefetch chunk 0
    float4 a00, a01, a10, a11;
    uint4 pb0, pb1, pbl0, pbl1;
    {
        const float* Arow = A1z + (row0 + lr) * (long long)lda1 + kh * 16;
        a00 = *(const float4*)(Arow);
        a01 = *(const float4*)(Arow + 4);
        a10 = *(const float4*)(Arow + 8);
        a11 = *(const float4*)(Arow + 12);
        if (bvalid) {
            pb0 = *(const uint4*)(Whz + boffg);
            pb1 = *(const uint4*)(Whz + boffg + 8);
            if (TERMS == 3) {
                pbl0 = *(const uint4*)(Wl + boffg);
                pbl1 = *(const uint4*)(Wl + boffg + 8);
            }
        }
    }

    for (int ch = 0; ch < nchunk; ch++) {
        const uint32_t bo = (uint32_t)(ch & 1) * BUFSZ;
        split8h(sAst + bo,      10240, a00, a01);
        split8h(sAst + bo + 16, 10240, a10, a11);
        if (bvalid) {
            STS128(sBst + bo,      pb0);
            STS128(sBst + bo + 16, pb1);
            if (TERMS == 3) {
                STS128(sBst + bo + BLO,      pbl0);
                STS128(sBst + bo + BLO + 16, pbl1);
            }
        }
        __syncthreads();

        if (ch + 1 < nchunk) {
            const int k0 = (ch + 1) * 32;
            const float* Arow = (k0 < K1)
                ? A1z + (row0 + lr) * (long long)lda1 + k0 + kh * 16
                : A2  + (row0 + lr) * (long long)lda2 + (k0 - K1) + kh * 16;
            a00 = *(const float4*)(Arow);
            a01 = *(const float4*)(Arow + 4);
            a10 = *(const float4*)(Arow + 8);
            a11 = *(const float4*)(Arow + 12);
            if (bvalid) {
                pb0 = *(const uint4*)(Whz + boffg + k0);
                pb1 = *(const uint4*)(Whz + boffg + k0 + 8);
                if (TERMS == 3) {
                    pbl0 = *(const uint4*)(Wl + boffg + k0);
                    pbl1 = *(const uint4*)(Wl + boffg + k0 + 8);
                }
            }
        }

#pragma unroll
        for (int khalf = 0; khalf < 2; khalf++) {
            const uint32_t kb = (uint32_t)khalf * 32 + bo;
            uint32_t Ah[2][4], Al[2][4];
#pragma unroll
            for (int mt = 0; mt < 2; mt++) {
                LDSM_X4(Ah[mt][0], Ah[mt][1], Ah[mt][2], Ah[mt][3], aoff[mt] + kb);
                LDSM_X4(Al[mt][0], Al[mt][1], Al[mt][2], Al[mt][3], aoff[mt] + kb + 10240);
            }
#pragma unroll
            for (int ntp = 0; ntp < NTP; ntp++) {
                uint32_t Bh[4], Bl[4];
                LDSM_X4(Bh[0], Bh[1], Bh[2], Bh[3], boff[ntp] + kb);
                if (TERMS == 3)
                    LDSM_X4(Bl[0], Bl[1], Bl[2], Bl[3], boff[ntp] + kb + BLO);
#pragma unroll
                for (int mt = 0; mt < 2; mt++) {
#pragma unroll
                    for (int nt2 = 0; nt2 < 2; nt2++) {
                        float* d = acc[mt][ntp * 2 + nt2];
                        mma16816h(d, Ah[mt], &Bh[nt2 * 2]);       // hi*Whi
                        mma16816h(d, Al[mt], &Bh[nt2 * 2]);       // lo*Whi
                        if (TERMS == 3)
                            mma16816h(d, Ah[mt], &Bl[nt2 * 2]);   // hi*Wlo
                    }
                }
            }
        }
    }

    const int g = lid >> 2, t = lid & 3;
    const float* biz = bias ? bias + (long long)z * bz : nullptr;
    float* Cz = HOUT ? nullptr : C + (long long)z * cz;
    __half* Chz = HOUT ? Ch + (long long)z * cz : nullptr;
#pragma unroll
    for (int mt = 0; mt < 2; mt++) {
        long long rA = row0 + warp_m * 32 + mt * 16 + g;
        long long rB = rA + 8;
#pragma unroll
        for (int nt = 0; nt < NT / 16; nt++) {
            int col = col0 + warp_n * (NT / 2) + nt * 8 + 2 * t;
            float b0 = biz ? biz[col] : 0.f;
            float b1 = biz ? biz[col + 1] : 0.f;
            float* d = acc[mt][nt];
            float o0 = d[0] + b0, o1 = d[1] + b1, o2 = d[2] + b0, o3 = d[3] + b1;
            if (HOUT) {
                *(__half2*)(Chz + rA * ldc + col) = __floats2half2_rn(o0, o1);
                *(__half2*)(Chz + rB * ldc + col) = __floats2half2_rn(o2, o3);
            } else {
                *(float2*)(Cz + rA * ldc + col) = make_float2(o0, o1);
                *(float2*)(Cz + rB * ldc + col) = make_float2(o2, o3);
            }
        }
    }
}

// -------------------- fp32 -> fp16 (round) ---------------------------------
__global__ __launch_bounds__(256)
void tofp16(const float* __restrict__ s, __half* __restrict__ d, int n)
{
    int i = (blockIdx.x * 256 + threadIdx.x) * 8;
    if (i >= n) return;
    float4 a = *(const float4*)(s + i);
    float4 b = *(const float4*)(s + i + 4);
    __half2 h0 = __floats2half2_rn(a.x, a.y), h1 = __floats2half2_rn(a.z, a.w);
    __half2 h2 = __floats2half2_rn(b.x, b.y), h3 = __floats2half2_rn(b.z, b.w);
    *(uint4*)(d + i) = make_uint4(*(uint32_t*)&h0, *(uint32_t*)&h1, *(uint32_t*)&h2, *(uint32_t*)&h3);
}

// ---- Q = node[:, 0, :] @ Wq_w^T + Wq_b; grid (Bb, 8), 4 thr/output --------
__global__ __launch_bounds__(256)
void q_kernel(const float* __restrict__ node, const float* __restrict__ Wq_w,
              const float* __restrict__ Wq_b)
{
    __shared__ __align__(16) float xs[512];
    const int b = blockIdx.x, part = blockIdx.y, tid = threadIdx.x;
    const float* xr = node + (long long)b * Nn * Cc;
    xs[tid]       = xr[tid];
    xs[tid + 256] = xr[tid + 256];
    __syncthreads();
    const int jj = tid >> 2;        // 0..63
    const int t4 = tid & 3;         // k-quarter
    const int j = part * 64 + jj;
    const float4* x4 = (const float4*)xs + t4 * 32;
    const float4* w4 = (const float4*)(Wq_w + (long long)j * 512) + t4 * 32;
    float acc0 = 0.f, acc1 = 0.f;
#pragma unroll 8
    for (int k = 0; k < 32; k += 2) {
        float4 w0 = w4[k], x0 = x4[k];
        float4 w1 = w4[k + 1], x1 = x4[k + 1];
        acc0 += w0.x*x0.x + w0.y*x0.y + w0.z*x0.z + w0.w*x0.w;
        acc1 += w1.x*x1.x + w1.y*x1.y + w1.z*x1.z + w1.w*x1.w;
    }
    float acc = acc0 + acc1;
    acc += __shfl_xor_sync(0xffffffffu, acc, 1);
    acc += __shfl_xor_sync(0xffffffffu, acc, 2);
    if (t4 == 0) g_Q[b * 512 + j] = acc + Wq_b[j];
}

// ------ Weff[b,e2,:] = sum_a Q[b,a,e2] * Wk_w[a*64+e2,:] -> fp16 -----------
__global__ __launch_bounds__(256)
void weff_kernel(const float* __restrict__ Wk_w, const float* __restrict__ Wk_b)
{
    __shared__ float Qs[512];
    const int b = blockIdx.x, part = blockIdx.y, tid = threadIdx.x;
    Qs[tid]       = g_Q[b * 512 + tid];
    Qs[tid + 256] = g_Q[b * 512 + 256 + tid];
    __syncthreads();
    const int i0 = part * 4096;
    for (int idx = i0 + tid; idx < i0 + 4096; idx += 256) {
        int e2 = idx >> 9, c = idx & 511;
        float acc = 0.f;
#pragma unroll
        for (int a = 0; a < 8; a++)
            acc += Qs[a * 64 + e2] * Wk_w[(long long)(a * 64 + e2) * 512 + c];
        g_WeffH[(long long)b * 32768 + idx] = __float2half_rn(acc);
    }
    if (part == 0 && tid < 64) {
        float acc = 0.f;
#pragma unroll
        for (int a = 0; a < 8; a++) acc += Qs[a * 64 + tid] * Wk_b[a * 64 + tid];
        g_beff[b * 64 + tid] = acc;
    }
}

// -------------------- weight prep ------------------------------------------
__global__ void prepsum(const float* __restrict__ nt_w, const float* __restrict__ nt_b,
                        const float* __restrict__ et_w2, const float* __restrict__ et_b2)
{
    int n = blockIdx.x, t = threadIdx.x;
    for (int k = t; k < 576; k += 256) {
        float v = (k < 512) ? nt_w[n * 512 + k] : et_w2[n * 64 + (k - 512)];
        __half hh = __float2half_rn(v);
        g_WsumH[n * 576 + k] = hh;
        g_WsumL[n * 576 + k] = __float2half_rn(v - __half2float(hh));
    }
    if (t == 0) g_bsum[n] = nt_b[n] + et_b2[n];
}

// ---- fused val + H12, 32 rows per block (weights amortized 4x) ------------
__global__ __launch_bounds__(256)
void val_h12_kernel(const float* __restrict__ edge, const float* __restrict__ emb1,
                    const float* __restrict__ emb2, const float* __restrict__ Wew,
                    const float* __restrict__ Wa_w1, const float* __restrict__ et_w1,
                    const float* __restrict__ et_b1)
{
    __shared__ float WewT[32 * 32];      // [j][e]
    __shared__ float er[32][32];
    __shared__ float vs[32][33];         // padded
    __shared__ float W12T[32][132];      // [e][h], padded
    __shared__ float b12s[128];
    const int tid = threadIdx.x;
    const long long row0 = (long long)blockIdx.x * 32;
    for (int i = tid; i < 1024; i += 256) WewT[(i & 31) * 32 + (i >> 5)] = Wew[i];
    for (int i = tid; i < 1024; i += 256) er[i >> 5][i & 31] = edge[row0 * 32 + i];
    for (int i = tid; i < 4096; i += 256) {
        int h = i >> 5, e = i & 31;
        W12T[e][h] = (h < 64) ? Wa_w1[h * 32 + e] : et_w1[(h - 64) * 32 + e];
    }
    if (tid < 128) b12s[tid] = (tid < 64) ? 0.f : et_b1[tid - 64];
    __syncthreads();

    {
        const int rb = tid >> 5, e = tid & 31;
        const float sc = 1.0507009873554805f, al = 1.6732632423543772f;
#pragma unroll
        for (int q = 0; q < 4; q++) {
            const int r = q * 8 + rb;
            const long long row = row0 + r;
            float ew = 0.f;
#pragma unroll
            for (int j = 0; j < 32; j++) ew += er[r][j] * WewT[j * 32 + e];
            float qk  = g_QK[row * 64 + e];
            float qkh = g_QK[row * 64 + 32 + e];
            float x = qk * ew;
            float rr = (x > 0.f) ? sqrtf(x) : -sqrtf(-x);
            float v = rr + qkh * emb1[row * 32 + e] + emb2[row * 32 + e];
            vs[r][e] = (v > 0.f) ? sc * v : sc * al * (expf(v) - 1.f);
        }
    }
    __syncthreads();

    const int h = tid & 127, half = tid >> 7;
    float w[32];
#pragma unroll
    for (int e = 0; e < 32; e++) w[e] = W12T[e][h];
    const float bb = b12s[h];
#pragma unroll
    for (int rp = 0; rp < 8; rp++) {
        const int r0 = half * 16 + rp * 2;
        float acc0 = bb, acc1 = bb;
#pragma unroll
        for (int e = 0; e < 32; e++) {
            acc0 = fmaf(vs[r0][e],     w[e], acc0);
            acc1 = fmaf(vs[r0 + 1][e], w[e], acc1);
        }
        float g0 = 0.5f * acc0 * (1.f + erff(acc0 * 0.70710678118654752f));
        float g1 = 0.5f * acc1 * (1.f + erff(acc1 * 0.70710678118654752f));
        g_H12[(row0 + r0) * 128 + h]     = g0;
        g_H12[(row0 + r0 + 1) * 128 + h] = g1;
    }
}

// ---- fused tail: branch-free (no max-subtraction; |logits| << 1) ----------
// Pass A: s += exp(x), u = max(u, |sm|*exp(x)). Pass B: mask + write + colsum.
__global__ __launch_bounds__(512)
void tail_kernel(float* __restrict__ d_tmp, float* __restrict__ outp)
{
    __shared__ float4 reds[16][32];
    __shared__ float4 redu[16][32];
    const int b = blockIdx.y, cb = blockIdx.x;
    const int slice = threadIdx.x >> 5, lane = threadIdx.x & 31;
    const long long lgbase  = (long long)b * 2048 * 128 + cb * 32 + lane;
    const long long tmpbase = (long long)b * 2047 * 128 + cb * 32 + lane;
    const uint2* LG = (const uint2*)g_logitsH;     // 4 halves per element
    const float4* SM = (const float4*)g_sum;
    float4* TMP = (float4*)d_tmp;
    const int n0 = 1 + slice * 128;
    const int n1 = min(2048, n0 + 128);

    float sx=0.f, sy=0.f, sz=0.f, sw=0.f;
    float ux=0.f, uy=0.f, uz=0.f, uw=0.f;
#pragma unroll 4
    for (int n = n0; n < n1; n++) {
        uint2 xr = LG[lgbase + (long long)n * 128];
        float2 x0 = __half22float2(*(__half2*)&xr.x);
        float2 x1 = __half22float2(*(__half2*)&xr.y);
        float4 sm = SM[lgbase + (long long)n * 128];
        float ex = __expf(x0.x), ey = __expf(x0.y);
        float ez = __expf(x1.x), ew = __expf(x1.y);
        sx += ex; sy += ey; sz += ez; sw += ew;
        ux = fmaxf(ux, fabsf(sm.x) * ex); uy = fmaxf(uy, fabsf(sm.y) * ey);
        uz = fmaxf(uz, fabsf(sm.z) * ez); uw = fmaxf(uw, fabsf(sm.w) * ew);
    }
    reds[slice][lane] = make_float4(sx, sy, sz, sw);
    redu[slice][lane] = make_float4(ux, uy, uz, uw);
    __syncthreads();
    float Sx=0.f, Sy=0.f, Sz=0.f, Sw=0.f;
    float Ux=0.f, Uy=0.f, Uz=0.f, Uw=0.f;
#pragma unroll
    for (int k = 0; k < 16; k++) {
        float4 fs = reds[k][lane];
        float4 fu = redu[k][lane];
        Sx += fs.x; Sy += fs.y; Sz += fs.z; Sw += fs.w;
        Ux = fmaxf(Ux, fu.x); Uy = fmaxf(Uy, fu.y);
        Uz = fmaxf(Uz, fu.z); Uw = fmaxf(Uw, fu.w);
    }
    const float ivx = 1.f / Sx, ivy = 1.f / Sy, ivz = 1.f / Sz, ivw = 1.f / Sw;
    const float tux = Ux * 0.1f, tuy = Uy * 0.1f, tuz = Uz * 0.1f, tuw = Uw * 0.1f;

    float cx=0.f, cy=0.f, cz2=0.f, cw=0.f;
#pragma unroll 4
    for (int n = n0; n < n1; n++) {
        uint2 xr = LG[lgbase + (long long)n * 128];
        float2 x0 = __half22float2(*(__half2*)&xr.x);
        float2 x1 = __half22float2(*(__half2*)&xr.y);
        float4 sm = SM[lgbase + (long long)n * 128];
        float uxx = sm.x * __expf(x0.x), uyy = sm.y * __expf(x0.y);
        float uzz = sm.z * __expf(x1.x), uww = sm.w * __expf(x1.y);
        float tx = (fabsf(uxx) >= tux) ? uxx * ivx : 0.f;
        float ty = (fabsf(uyy) >= tuy) ? uyy * ivy : 0.f;
        float tz = (fabsf(uzz) >= tuz) ? uzz * ivz : 0.f;
        float tw = (fabsf(uww) >= tuw) ? uww * ivw : 0.f;
        TMP[tmpbase + (long long)(n - 1) * 128] = make_float4(tx, ty, tz, tw);
        cx += tx; cy += ty; cz2 += tz; cw += tw;
    }
    reds[slice][lane] = make_float4(cx, cy, cz2, cw);
    __syncthreads();
    if (slice == 0) {
        float4 tot = make_float4(0.f, 0.f, 0.f, 0.f);
#pragma unroll
        for (int k = 0; k < 16; k++) {
            float4 f = reds[k][lane];
            tot.x += f.x; tot.y += f.y; tot.z += f.z; tot.w += f.w;
        }
        ((float4*)outp)[(long long)b * 128 + cb * 32 + lane] = tot;
    }
}

// ---------------------------------------------------------------------------
extern "C" void kernel_launch(void* const* d_in, const int* in_sizes, int n_in,
                              void* d_out, int out_size)
{
    const float* node  = (const float*)d_in[0];
    const float* edge  = (const float*)d_in[1];
    const float* emb1  = (const float*)d_in[2];
    const float* emb2  = (const float*)d_in[3];
    const float* Wq_w  = (const float*)d_in[4];
    const float* Wq_b  = (const float*)d_in[5];
    const float* Wk_w  = (const float*)d_in[6];
    const float* Wk_b  = (const float*)d_in[7];
    const float* Wew_w = (const float*)d_in[8];
    const float* Wa_w1 = (const float*)d_in[9];
    const float* Wa_w2 = (const float*)d_in[10];
    const float* nt_w  = (const float*)d_in[11];
    const float* nt_b  = (const float*)d_in[12];
    const float* et_w1 = (const float*)d_in[13];
    const float* et_b1 = (const float*)d_in[14];
    const float* et_w2 = (const float*)d_in[15];
    const float* et_b2 = (const float*)d_in[16];

    float* outp  = (float*)d_out;            // (B, IN) first
    float* d_tmp = outp + Bb * INc;          // then (B, N-1, IN)

    void *pSum, *pLGH, *pH12, *pQK, *pBeff, *pBsum;
    void *pWeH, *pWsH, *pWsL, *pWa2H;
    cudaGetSymbolAddress(&pSum,  g_sum);
    cudaGetSymbolAddress(&pLGH,  g_logitsH);
    cudaGetSymbolAddress(&pH12,  g_H12);
    cudaGetSymbolAddress(&pQK,   g_QK);
    cudaGetSymbolAddress(&pBeff, g_beff);
    cudaGetSymbolAddress(&pBsum, g_bsum);
    cudaGetSymbolAddress(&pWeH,  g_WeffH);
    cudaGetSymbolAddress(&pWsH,  g_WsumH);
    cudaGetSymbolAddress(&pWsL,  g_WsumL);
    cudaGetSymbolAddress(&pWa2H, g_Wa2H);

    // dynamic smem limits (idempotent host calls; no allocation)
    cudaFuncSetAttribute(mma_gemm<64, 2, false>,  cudaFuncAttributeMaxDynamicSharedMemorySize, 51200);
    cudaFuncSetAttribute(mma_gemm<128, 2, true>,  cudaFuncAttributeMaxDynamicSharedMemorySize, 61440);
    cudaFuncSetAttribute(mma_gemm<128, 3, false>, cudaFuncAttributeMaxDynamicSharedMemorySize, 81920);

    // weight prep (tiny, one-time per launch)
    tofp16<<<16, 256>>>(Wa_w2, (__half*)pWa2H, 512 * 64);
    prepsum<<<512, 256>>>(nt_w, nt_b, et_w2, et_b2);

    // Q -> Weff/beff -> QK (batched N=64 GEMM, K=512, 2-term)
    q_kernel<<<dim3(Bb, 8), 256>>>(node, Wq_w, Wq_b);
    weff_kernel<<<dim3(Bb, 8), 256>>>(Wk_w, Wk_b);
    mma_gemm<64, 2, false><<<dim3(1, Nn / 128, Bb), 256, 51200>>>(
        node, Cc, Cc, nullptr, 0, 0,
        (const __half*)pWeH, nullptr, (const float*)pBeff,
        (float*)pQK, nullptr, 64,
        (long long)Nn * Cc, 64LL * 512, 64LL, (long long)Nn * 64);

    // fused val + H12 (32 rows/block)
    val_h12_kernel<<<Mtot / 32, 256>>>(edge, emb1, emb2, Wew_w, Wa_w1, et_w1, et_b1);

    // logits = H1 @ Wa_w2^T  (M x 512, K=64, 2-term, fp16 output)
    mma_gemm<128, 2, true><<<dim3(4, Mtot / 128, 1), 256, 61440>>>(
        (const float*)pH12, 128, 64, nullptr, 0, 0,
        (const __half*)pWa2H, nullptr, nullptr,
        nullptr, (__half*)pLGH, INc, 0, 0, 0, 0);

    // sum = node @ nt_w^T + H2 @ et_w2^T + (nt_b + et_b2)  (K=576, 3-term)
    mma_gemm<128, 3, false><<<dim3(4, Mtot / 128, 1), 256, 81920>>>(
        node, Cc, Cc, (const float*)pH12 + 64, 128, 64,
        (const __half*)pWsH, (const __half*)pWsL, (const float*)pBsum,
        (float*)pSum, nullptr, INc, 0, 0, 0, 0);

    // fused softmax + combine + threshold + mask + colsum (branch-free)
    tail_kernel<<<dim3(4, Bb), 512>>>(d_tmp, outp);
}

// round 15
// speedup vs baseline: 1.3540x; 1.0026x over previous
#include <cuda_runtime.h>
#include <cuda_fp16.h>
#include <math.h>
#include <stdint.h>

#define Bb   64
#define Nn   2048
#define Cc   512
#define Ee   32
#define Ac   8
#define INc  512
#define Hc   64
#define Mtot (Bb*Nn)

// -------------------- device scratch (static; allocation-free) -------------
__device__ float  g_sum    [(long long)Mtot*INc];
__device__ __half g_logitsH[(long long)Mtot*INc];
__device__ float  g_H12    [(long long)Mtot*128];   // [H1 | H2] fp32
__device__ float  g_QK     [(long long)Mtot*64];
__device__ float  g_Q      [Bb*512];
__device__ float  g_beff   [Bb*64];
__device__ float  g_bsum   [512];
__device__ __half g_WeffH  [Bb*64*512];
__device__ __half g_WsumH  [512*576];
__device__ __half g_WsumL  [512*576];
__device__ __half g_Wa2H   [512*64];

// ========================== helpers ========================================
__device__ __forceinline__ uint32_t smem_u32(const void* p) {
    uint32_t a;
    asm("{ .reg .u64 t; cvta.to.shared.u64 t, %1; cvt.u32.u64 %0, t; }" : "=r"(a) : "l"(p));
    return a;
}
// 8 fp32 -> hi f16x8 (16B at addr), lo f16x8 (16B at addr+lo_off)
__device__ __forceinline__ void split8h(uint32_t addr, uint32_t lo_off, float4 a0, float4 a1) {
    __half2 h0 = __floats2half2_rn(a0.x, a0.y);
    __half2 h1 = __floats2half2_rn(a0.z, a0.w);
    __half2 h2 = __floats2half2_rn(a1.x, a1.y);
    __half2 h3 = __floats2half2_rn(a1.z, a1.w);
    float2 f0 = __half22float2(h0), f1 = __half22float2(h1);
    float2 f2 = __half22float2(h2), f3 = __half22float2(h3);
    __half2 l0 = __floats2half2_rn(a0.x - f0.x, a0.y - f0.y);
    __half2 l1 = __floats2half2_rn(a0.z - f1.x, a0.w - f1.y);
    __half2 l2 = __floats2half2_rn(a1.x - f2.x, a1.y - f2.y);
    __half2 l3 = __floats2half2_rn(a1.z - f3.x, a1.w - f3.y);
    asm volatile("st.shared.v4.b32 [%0], {%1,%2,%3,%4};"
        :: "r"(addr), "r"(*(uint32_t*)&h0), "r"(*(uint32_t*)&h1), "r"(*(uint32_t*)&h2), "r"(*(uint32_t*)&h3));
    asm volatile("st.shared.v4.b32 [%0], {%1,%2,%3,%4};"
        :: "r"(addr + lo_off), "r"(*(uint32_t*)&l0), "r"(*(uint32_t*)&l1), "r"(*(uint32_t*)&l2), "r"(*(uint32_t*)&l3));
}
#define LDSM_X4(r0, r1, r2, r3, addr) \
    asm volatile("ldmatrix.sync.aligned.m8n8.x4.shared.b16 {%0,%1,%2,%3}, [%4];" \
        : "=r"(r0), "=r"(r1), "=r"(r2), "=r"(r3) : "r"(addr))
__device__ __forceinline__ void mma16816h(float d[4], const uint32_t a[4], const uint32_t b[2]) {
    asm volatile("mma.sync.aligned.m16n8k16.row.col.f32.f16.f16.f32 "
        "{%0,%1,%2,%3},{%4,%5,%6,%7},{%8,%9},{%0,%1,%2,%3};"
        : "+f"(d[0]), "+f"(d[1]), "+f"(d[2]), "+f"(d[3])
        : "r"(a[0]), "r"(a[1]), "r"(a[2]), "r"(a[3]), "r"(b[0]), "r"(b[1]));
}
#define STS128(addr, v) \
    asm volatile("st.shared.v4.b32 [%0], {%1,%2,%3,%4};" \
        :: "r"(addr), "r"((v).x), "r"((v).y), "r"((v).z), "r"((v).w))

// ===== mixed-term GEMM, double-buffered smem (1 sync per chunk) =============
template<int NT, int TERMS, bool HOUT>
__global__ __launch_bounds__(256, 2)
void mma_gemm(const float* __restrict__ A1, int lda1, int K1,
              const float* __restrict__ A2, int lda2, int K2,
              const __half* __restrict__ Wh, const __half* __restrict__ Wl,
              const float* __restrict__ bias,
              float* __restrict__ C, __half* __restrict__ Ch, int ldc,
              long long az, long long wz, long long bz, long long cz)
{
    constexpr uint32_t BLO = NT * 80;
    constexpr int NBPL = (TERMS == 3) ? 2 : 1;
    constexpr uint32_t BUFSZ = 2 * 10240 + NBPL * NT * 80;
    extern __shared__ __align__(128) uint8_t smem_dyn[];
    const uint32_t SA = smem_u32(smem_dyn);
    const uint32_t SB = SA + 20480;
    const int Kt = K1 + K2;
    const int tid = threadIdx.x;
    const int wid = tid >> 5, lid = tid & 31;
    const int warp_m = wid & 3, warp_n = wid >> 2;
    const long long row0 = (long long)blockIdx.y * 128;
    const int col0 = blockIdx.x * NT;
    const int z = blockIdx.z;
    const float*  A1z = A1 + (long long)z * az;
    const __half* Whz = Wh + (long long)z * wz;

    const int lr = tid >> 1, kh = tid & 1;
    const uint32_t sAst = SA + (uint32_t)lr * 80 + (uint32_t)kh * 32;
    const uint32_t sBst = SB + (uint32_t)lr * 80 + (uint32_t)kh * 32;
    const bool bvalid = lr < NT;
    const long long boffg = (long long)(col0 + lr) * Kt + kh * 16;

    uint32_t aoff[2];
#pragma unroll
    for (int mt = 0; mt < 2; mt++) {
        int rowm = warp_m * 32 + mt * 16 + (lid & 7) + ((lid >> 3) & 1) * 8;
        aoff[mt] = SA + (uint32_t)rowm * 80 + (uint32_t)((lid >> 4) & 1) * 16;
    }
    constexpr int NTP = NT / 32;
    uint32_t boff[NTP];
#pragma unroll
    for (int ntp = 0; ntp < NTP; ntp++) {
        int rown = warp_n * (NT / 2) + ntp * 16 + (lid & 7) + ((lid >> 4) & 1) * 8;
        boff[ntp] = SB + (uint32_t)rown * 80 + (uint32_t)((lid >> 3) & 1) * 16;
    }

    float acc[2][NT / 16][4];
#pragma unroll
    for (int i = 0; i < 2; i++)
#pragma unroll
        for (int j = 0; j < NT / 16; j++)
#pragma unroll
            for (int q = 0; q < 4; q++) acc[i][j][q] = 0.f;

    const int nchunk = Kt >> 5;

    float4 a00, a01, a10, a11;
    uint4 pb0, pb1, pbl0, pbl1;
    {
        const float* Arow = A1z + (row0 + lr) * (long long)lda1 + kh * 16;
        a00 = *(const float4*)(Arow);
        a01 = *(const float4*)(Arow + 4);
        a10 = *(const float4*)(Arow + 8);
        a11 = *(const float4*)(Arow + 12);
        if (bvalid) {
            pb0 = *(const uint4*)(Whz + boffg);
            pb1 = *(const uint4*)(Whz + boffg + 8);
            if (TERMS == 3) {
                pbl0 = *(const uint4*)(Wl + boffg);
                pbl1 = *(const uint4*)(Wl + boffg + 8);
            }
        }
    }

    for (int ch = 0; ch < nchunk; ch++) {
        const uint32_t bo = (uint32_t)(ch & 1) * BUFSZ;
        split8h(sAst + bo,      10240, a00, a01);
        split8h(sAst + bo + 16, 10240, a10, a11);
        if (bvalid) {
            STS128(sBst + bo,      pb0);
            STS128(sBst + bo + 16, pb1);
            if (TERMS == 3) {
                STS128(sBst + bo + BLO,      pbl0);
                STS128(sBst + bo + BLO + 16, pbl1);
            }
        }
        __syncthreads();

        if (ch + 1 < nchunk) {
            const int k0 = (ch + 1) * 32;
            const float* Arow = (k0 < K1)
                ? A1z + (row0 + lr) * (long long)lda1 + k0 + kh * 16
                : A2  + (row0 + lr) * (long long)lda2 + (k0 - K1) + kh * 16;
            a00 = *(const float4*)(Arow);
            a01 = *(const float4*)(Arow + 4);
            a10 = *(const float4*)(Arow + 8);
            a11 = *(const float4*)(Arow + 12);
            if (bvalid) {
                pb0 = *(const uint4*)(Whz + boffg + k0);
                pb1 = *(const uint4*)(Whz + boffg + k0 + 8);
                if (TERMS == 3) {
                    pbl0 = *(const uint4*)(Wl + boffg + k0);
                    pbl1 = *(const uint4*)(Wl + boffg + k0 + 8);
                }
            }
        }

#pragma unroll
        for (int khalf = 0; khalf < 2; khalf++) {
            const uint32_t kb = (uint32_t)khalf * 32 + bo;
            uint32_t Ah[2][4], Al[2][4];
#pragma unroll
            for (int mt = 0; mt < 2; mt++) {
                LDSM_X4(Ah[mt][0], Ah[mt][1], Ah[mt][2], Ah[mt][3], aoff[mt] + kb);
                LDSM_X4(Al[mt][0], Al[mt][1], Al[mt][2], Al[mt][3], aoff[mt] + kb + 10240);
            }
#pragma unroll
            for (int ntp = 0; ntp < NTP; ntp++) {
                uint32_t Bh[4], Bl[4];
                LDSM_X4(Bh[0], Bh[1], Bh[2], Bh[3], boff[ntp] + kb);
                if (TERMS == 3)
                    LDSM_X4(Bl[0], Bl[1], Bl[2], Bl[3], boff[ntp] + kb + BLO);
#pragma unroll
                for (int mt = 0; mt < 2; mt++) {
#pragma unroll
                    for (int nt2 = 0; nt2 < 2; nt2++) {
                        float* d = acc[mt][ntp * 2 + nt2];
                        mma16816h(d, Ah[mt], &Bh[nt2 * 2]);
                        mma16816h(d, Al[mt], &Bh[nt2 * 2]);
                        if (TERMS == 3)
                            mma16816h(d, Ah[mt], &Bl[nt2 * 2]);
                    }
                }
            }
        }
    }

    const int g = lid >> 2, t = lid & 3;
    const float* biz = bias ? bias + (long long)z * bz : nullptr;
    float* Cz = HOUT ? nullptr : C + (long long)z * cz;
    __half* Chz = HOUT ? Ch + (long long)z * cz : nullptr;
#pragma unroll
    for (int mt = 0; mt < 2; mt++) {
        long long rA = row0 + warp_m * 32 + mt * 16 + g;
        long long rB = rA + 8;
#pragma unroll
        for (int nt = 0; nt < NT / 16; nt++) {
            int col = col0 + warp_n * (NT / 2) + nt * 8 + 2 * t;
            float b0 = biz ? biz[col] : 0.f;
            float b1 = biz ? biz[col + 1] : 0.f;
            float* d = acc[mt][nt];
            float o0 = d[0] + b0, o1 = d[1] + b1, o2 = d[2] + b0, o3 = d[3] + b1;
            if (HOUT) {
                *(__half2*)(Chz + rA * ldc + col) = __floats2half2_rn(o0, o1);
                *(__half2*)(Chz + rB * ldc + col) = __floats2half2_rn(o2, o3);
            } else {
                *(float2*)(Cz + rA * ldc + col) = make_float2(o0, o1);
                *(float2*)(Cz + rB * ldc + col) = make_float2(o2, o3);
            }
        }
    }
}

// -------------------- fp32 -> fp16 (round) ---------------------------------
__global__ __launch_bounds__(256)
void tofp16(const float* __restrict__ s, __half* __restrict__ d, int n)
{
    int i = (blockIdx.x * 256 + threadIdx.x) * 8;
    if (i >= n) return;
    float4 a = *(const float4*)(s + i);
    float4 b = *(const float4*)(s + i + 4);
    __half2 h0 = __floats2half2_rn(a.x, a.y), h1 = __floats2half2_rn(a.z, a.w);
    __half2 h2 = __floats2half2_rn(b.x, b.y), h3 = __floats2half2_rn(b.z, b.w);
    *(uint4*)(d + i) = make_uint4(*(uint32_t*)&h0, *(uint32_t*)&h1, *(uint32_t*)&h2, *(uint32_t*)&h3);
}

// ---- Q = node[:, 0, :] @ Wq_w^T + Wq_b; grid (Bb, 8), 4 thr/output --------
__global__ __launch_bounds__(256)
void q_kernel(const float* __restrict__ node, const float* __restrict__ Wq_w,
              const float* __restrict__ Wq_b)
{
    __shared__ __align__(16) float xs[512];
    const int b = blockIdx.x, part = blockIdx.y, tid = threadIdx.x;
    const float* xr = node + (long long)b * Nn * Cc;
    xs[tid]       = xr[tid];
    xs[tid + 256] = xr[tid + 256];
    __syncthreads();
    const int jj = tid >> 2;
    const int t4 = tid & 3;
    const int j = part * 64 + jj;
    const float4* x4 = (const float4*)xs + t4 * 32;
    const float4* w4 = (const float4*)(Wq_w + (long long)j * 512) + t4 * 32;
    float acc0 = 0.f, acc1 = 0.f;
#pragma unroll 8
    for (int k = 0; k < 32; k += 2) {
        float4 w0 = w4[k], x0 = x4[k];
        float4 w1 = w4[k + 1], x1 = x4[k + 1];
        acc0 += w0.x*x0.x + w0.y*x0.y + w0.z*x0.z + w0.w*x0.w;
        acc1 += w1.x*x1.x + w1.y*x1.y + w1.z*x1.z + w1.w*x1.w;
    }
    float acc = acc0 + acc1;
    acc += __shfl_xor_sync(0xffffffffu, acc, 1);
    acc += __shfl_xor_sync(0xffffffffu, acc, 2);
    if (t4 == 0) g_Q[b * 512 + j] = acc + Wq_b[j];
}

// ------ Weff[b,e2,:] = sum_a Q[b,a,e2] * Wk_w[a*64+e2,:] -> fp16 -----------
__global__ __launch_bounds__(256)
void weff_kernel(const float* __restrict__ Wk_w, const float* __restrict__ Wk_b)
{
    __shared__ float Qs[512];
    const int b = blockIdx.x, part = blockIdx.y, tid = threadIdx.x;
    Qs[tid]       = g_Q[b * 512 + tid];
    Qs[tid + 256] = g_Q[b * 512 + 256 + tid];
    __syncthreads();
    const int i0 = part * 4096;
    for (int idx = i0 + tid; idx < i0 + 4096; idx += 256) {
        int e2 = idx >> 9, c = idx & 511;
        float acc = 0.f;
#pragma unroll
        for (int a = 0; a < 8; a++)
            acc += Qs[a * 64 + e2] * Wk_w[(long long)(a * 64 + e2) * 512 + c];
        g_WeffH[(long long)b * 32768 + idx] = __float2half_rn(acc);
    }
    if (part == 0 && tid < 64) {
        float acc = 0.f;
#pragma unroll
        for (int a = 0; a < 8; a++) acc += Qs[a * 64 + tid] * Wk_b[a * 64 + tid];
        g_beff[b * 64 + tid] = acc;
    }
}

// -------------------- weight prep ------------------------------------------
__global__ void prepsum(const float* __restrict__ nt_w, const float* __restrict__ nt_b,
                        const float* __restrict__ et_w2, const float* __restrict__ et_b2)
{
    int n = blockIdx.x, t = threadIdx.x;
    for (int k = t; k < 576; k += 256) {
        float v = (k < 512) ? nt_w[n * 512 + k] : et_w2[n * 64 + (k - 512)];
        __half hh = __float2half_rn(v);
        g_WsumH[n * 576 + k] = hh;
        g_WsumL[n * 576 + k] = __float2half_rn(v - __half2float(hh));
    }
    if (t == 0) g_bsum[n] = nt_b[n] + et_b2[n];
}

// ---- fused val + H12, 32 rows per block ------------------------------------
__global__ __launch_bounds__(256)
void val_h12_kernel(const float* __restrict__ edge, const float* __restrict__ emb1,
                    const float* __restrict__ emb2, const float* __restrict__ Wew,
                    const float* __restrict__ Wa_w1, const float* __restrict__ et_w1,
                    const float* __restrict__ et_b1)
{
    __shared__ float WewT[32 * 32];
    __shared__ float er[32][32];
    __shared__ float vs[32][33];
    __shared__ float W12T[32][132];
    __shared__ float b12s[128];
    const int tid = threadIdx.x;
    const long long row0 = (long long)blockIdx.x * 32;
    for (int i = tid; i < 1024; i += 256) WewT[(i & 31) * 32 + (i >> 5)] = Wew[i];
    for (int i = tid; i < 1024; i += 256) er[i >> 5][i & 31] = edge[row0 * 32 + i];
    for (int i = tid; i < 4096; i += 256) {
        int h = i >> 5, e = i & 31;
        W12T[e][h] = (h < 64) ? Wa_w1[h * 32 + e] : et_w1[(h - 64) * 32 + e];
    }
    if (tid < 128) b12s[tid] = (tid < 64) ? 0.f : et_b1[tid - 64];
    __syncthreads();

    {
        const int rb = tid >> 5, e = tid & 31;
        const float sc = 1.0507009873554805f, al = 1.6732632423543772f;
#pragma unroll
        for (int q = 0; q < 4; q++) {
            const int r = q * 8 + rb;
            const long long row = row0 + r;
            float ew = 0.f;
#pragma unroll
            for (int j = 0; j < 32; j++) ew += er[r][j] * WewT[j * 32 + e];
            float qk  = g_QK[row * 64 + e];
            float qkh = g_QK[row * 64 + 32 + e];
            float x = qk * ew;
            float rr = (x > 0.f) ? sqrtf(x) : -sqrtf(-x);
            float v = rr + qkh * emb1[row * 32 + e] + emb2[row * 32 + e];
            vs[r][e] = (v > 0.f) ? sc * v : sc * al * (expf(v) - 1.f);
        }
    }
    __syncthreads();

    const int h = tid & 127, half = tid >> 7;
    float w[32];
#pragma unroll
    for (int e = 0; e < 32; e++) w[e] = W12T[e][h];
    const float bb = b12s[h];
#pragma unroll
    for (int rp = 0; rp < 8; rp++) {
        const int r0 = half * 16 + rp * 2;
        float acc0 = bb, acc1 = bb;
#pragma unroll
        for (int e = 0; e < 32; e++) {
            acc0 = fmaf(vs[r0][e],     w[e], acc0);
            acc1 = fmaf(vs[r0 + 1][e], w[e], acc1);
        }
        float g0 = 0.5f * acc0 * (1.f + erff(acc0 * 0.70710678118654752f));
        float g1 = 0.5f * acc1 * (1.f + erff(acc1 * 0.70710678118654752f));
        g_H12[(row0 + r0) * 128 + h]     = g0;
        g_H12[(row0 + r0 + 1) * 128 + h] = g1;
    }
}

// ---- fused tail: branch-free -----------------------------------------------
__global__ __launch_bounds__(512)
void tail_kernel(float* __restrict__ d_tmp, float* __restrict__ outp)
{
    __shared__ float4 reds[16][32];
    __shared__ float4 redu[16][32];
    const int b = blockIdx.y, cb = blockIdx.x;
    const int slice = threadIdx.x >> 5, lane = threadIdx.x & 31;
    const long long lgbase  = (long long)b * 2048 * 128 + cb * 32 + lane;
    const long long tmpbase = (long long)b * 2047 * 128 + cb * 32 + lane;
    const uint2* LG = (const uint2*)g_logitsH;
    const float4* SM = (const float4*)g_sum;
    float4* TMP = (float4*)d_tmp;
    const int n0 = 1 + slice * 128;
    const int n1 = min(2048, n0 + 128);

    float sx=0.f, sy=0.f, sz=0.f, sw=0.f;
    float ux=0.f, uy=0.f, uz=0.f, uw=0.f;
#pragma unroll 4
    for (int n = n0; n < n1; n++) {
        uint2 xr = LG[lgbase + (long long)n * 128];
        float2 x0 = __half22float2(*(__half2*)&xr.x);
        float2 x1 = __half22float2(*(__half2*)&xr.y);
        float4 sm = SM[lgbase + (long long)n * 128];
        float ex = __expf(x0.x), ey = __expf(x0.y);
        float ez = __expf(x1.x), ew = __expf(x1.y);
        sx += ex; sy += ey; sz += ez; sw += ew;
        ux = fmaxf(ux, fabsf(sm.x) * ex); uy = fmaxf(uy, fabsf(sm.y) * ey);
        uz = fmaxf(uz, fabsf(sm.z) * ez); uw = fmaxf(uw, fabsf(sm.w) * ew);
    }
    reds[slice][lane] = make_float4(sx, sy, sz, sw);
    redu[slice][lane] = make_float4(ux, uy, uz, uw);
    __syncthreads();
    float Sx=0.f, Sy=0.f, Sz=0.f, Sw=0.f;
    float Ux=0.f, Uy=0.f, Uz=0.f, Uw=0.f;
#pragma unroll
    for (int k = 0; k < 16; k++) {
        float4 fs = reds[k][lane];
        float4 fu = redu[k][lane];
        Sx += fs.x; Sy += fs.y; Sz += fs.z; Sw += fs.w;
        Ux = fmaxf(Ux, fu.x); Uy = fmaxf(Uy, fu.y);
        Uz = fmaxf(Uz, fu.z); Uw = fmaxf(Uw, fu.w);
    }
    const float ivx = 1.f / Sx, ivy = 1.f / Sy, ivz = 1.f / Sz, ivw = 1.f / Sw;
    const float tux = Ux * 0.1f, tuy = Uy * 0.1f, tuz = Uz * 0.1f, tuw = Uw * 0.1f;

    float cx=0.f, cy=0.f, cz2=0.f, cw=0.f;
#pragma unroll 4
    for (int n = n0; n < n1; n++) {
        uint2 xr = LG[lgbase + (long long)n * 128];
        float2 x0 = __half22float2(*(__half2*)&xr.x);
        float2 x1 = __half22float2(*(__half2*)&xr.y);
        float4 sm = SM[lgbase + (long long)n * 128];
        float uxx = sm.x * __expf(x0.x), uyy = sm.y * __expf(x0.y);
        float uzz = sm.z * __expf(x1.x), uww = sm.w * __expf(x1.y);
        float tx = (fabsf(uxx) >= tux) ? uxx * ivx : 0.f;
        float ty = (fabsf(uyy) >= tuy) ? uyy * ivy : 0.f;
        float tz = (fabsf(uzz) >= tuz) ? uzz * ivz : 0.f;
        float tw = (fabsf(uww) >= tuw) ? uww * ivw : 0.f;
        TMP[tmpbase + (long long)(n - 1) * 128] = make_float4(tx, ty, tz, tw);
        cx += tx; cy += ty; cz2 += tz; cw += tw;
    }
    reds[slice][lane] = make_float4(cx, cy, cz2, cw);
    __syncthreads();
    if (slice == 0) {
        float4 tot = make_float4(0.f, 0.f, 0.f, 0.f);
#pragma unroll
        for (int k = 0; k < 16; k++) {
            float4 f = reds[k][lane];
            tot.x += f.x; tot.y += f.y; tot.z += f.z; tot.w += f.w;
        }
        ((float4*)outp)[(long long)b * 128 + cb * 32 + lane] = tot;
    }
}

// ---------------------------------------------------------------------------
extern "C" void kernel_launch(void* const* d_in, const int* in_sizes, int n_in,
                              void* d_out, int out_size)
{
    const float* node  = (const float*)d_in[0];
    const float* edge  = (const float*)d_in[1];
    const float* emb1  = (const float*)d_in[2];
    const float* emb2  = (const float*)d_in[3];
    const float* Wq_w  = (const float*)d_in[4];
    const float* Wq_b  = (const float*)d_in[5];
    const float* Wk_w  = (const float*)d_in[6];
    const float* Wk_b  = (const float*)d_in[7];
    const float* Wew_w = (const float*)d_in[8];
    const float* Wa_w1 = (const float*)d_in[9];
    const float* Wa_w2 = (const float*)d_in[10];
    const float* nt_w  = (const float*)d_in[11];
    const float* nt_b  = (const float*)d_in[12];
    const float* et_w1 = (const float*)d_in[13];
    const float* et_b1 = (const float*)d_in[14];
    const float* et_w2 = (const float*)d_in[15];
    const float* et_b2 = (const float*)d_in[16];

    float* outp  = (float*)d_out;            // (B, IN) first
    float* d_tmp = outp + Bb * INc;          // then (B, N-1, IN)

    void *pSum, *pLGH, *pH12, *pQK, *pBeff, *pBsum;
    void *pWeH, *pWsH, *pWsL, *pWa2H;
    cudaGetSymbolAddress(&pSum,  g_sum);
    cudaGetSymbolAddress(&pLGH,  g_logitsH);
    cudaGetSymbolAddress(&pH12,  g_H12);
    cudaGetSymbolAddress(&pQK,   g_QK);
    cudaGetSymbolAddress(&pBeff, g_beff);
    cudaGetSymbolAddress(&pBsum, g_bsum);
    cudaGetSymbolAddress(&pWeH,  g_WeffH);
    cudaGetSymbolAddress(&pWsH,  g_WsumH);
    cudaGetSymbolAddress(&pWsL,  g_WsumL);
    cudaGetSymbolAddress(&pWa2H, g_Wa2H);

    cudaFuncSetAttribute(mma_gemm<64, 2, false>,  cudaFuncAttributeMaxDynamicSharedMemorySize, 51200);
    cudaFuncSetAttribute(mma_gemm<128, 2, true>,  cudaFuncAttributeMaxDynamicSharedMemorySize, 61440);
    cudaFuncSetAttribute(mma_gemm<128, 3, false>, cudaFuncAttributeMaxDynamicSharedMemorySize, 81920);

    // side stream + fork/join events (created once; host-side infra only)
    static cudaStream_t s2 = nullptr;
    static cudaEvent_t evA = nullptr, evB = nullptr, evC = nullptr, evD = nullptr;
    if (!s2) {
        cudaStreamCreateWithFlags(&s2, cudaStreamNonBlocking);
        cudaEventCreateWithFlags(&evA, cudaEventDisableTiming);
        cudaEventCreateWithFlags(&evB, cudaEventDisableTiming);
        cudaEventCreateWithFlags(&evC, cudaEventDisableTiming);
        cudaEventCreateWithFlags(&evD, cudaEventDisableTiming);
    }

    // fork: weight prep on s2 (independent of Q/Weff/QK chain)
    cudaEventRecord(evA, 0);
    cudaStreamWaitEvent(s2, evA, 0);
    tofp16<<<16, 256, 0, s2>>>(Wa_w2, (__half*)pWa2H, 512 * 64);
    prepsum<<<512, 256, 0, s2>>>(nt_w, nt_b, et_w2, et_b2);
    cudaEventRecord(evB, s2);

    // main chain on default stream
    q_kernel<<<dim3(Bb, 8), 256>>>(node, Wq_w, Wq_b);
    weff_kernel<<<dim3(Bb, 8), 256>>>(Wk_w, Wk_b);
    mma_gemm<64, 2, false><<<dim3(1, Nn / 128, Bb), 256, 51200>>>(
        node, Cc, Cc, nullptr, 0, 0,
        (const __half*)pWeH, nullptr, (const float*)pBeff,
        (float*)pQK, nullptr, 64,
        (long long)Nn * Cc, 64LL * 512, 64LL, (long long)Nn * 64);
    val_h12_kernel<<<Mtot / 32, 256>>>(edge, emb1, emb2, Wew_w, Wa_w1, et_w1, et_b1);

    // fork: logits GEMM on s2 (needs H12 from default, Wa2H from s2)
    cudaEventRecord(evC, 0);
    cudaStreamWaitEvent(s2, evC, 0);
    mma_gemm<128, 2, true><<<dim3(4, Mtot / 128, 1), 256, 61440, s2>>>(
        (const float*)pH12, 128, 64, nullptr, 0, 0,
        (const __half*)pWa2H, nullptr, nullptr,
        nullptr, (__half*)pLGH, INc, 0, 0, 0, 0);
    cudaEventRecord(evD, s2);

    // sum GEMM on default (needs prepsum from s2)
    cudaStreamWaitEvent(0, evB, 0);
    mma_gemm<128, 3, false><<<dim3(4, Mtot / 128, 1), 256, 81920>>>(
        node, Cc, Cc, (const float*)pH12 + 64, 128, 64,
        (const __half*)pWsH, (const __half*)pWsL, (const float*)pBsum,
        (float*)pSum, nullptr, INc, 0, 0, 0, 0);

    // join: tail needs both GEMMs
    cudaStreamWaitEvent(0, evD, 0);
    tail_kernel<<<dim3(4, Bb), 512>>>(d_tmp, outp);
}